// round 2
// baseline (speedup 1.0000x reference)
#include <cuda_runtime.h>
#include <cuda_bf16.h>
#include <math.h>

#define SRC   2048
#define TGT   2048
#define BATCH 16
#define HD    512

// -------- scratch (device globals; no runtime allocation) --------
__device__ float g_OE[(size_t)BATCH * SRC * HD];               // [B][S][H]  67 MB
__device__ float g_Q [(size_t)BATCH * TGT * HD];               // [B][T][H]  67 MB
__device__ float g_ATT[(size_t)BATCH * TGT * SRC];             // [B][T][S] 268 MB

// ----------------------------------------------------------------
// prep: oe[b][s][h] = out_e[s][b][h] + out_e[s][b][H+h]
//       q [b][t][h] = out_d[t][b][h]          (SRC == TGT)
// ----------------------------------------------------------------
__global__ __launch_bounds__(256) void prep_kernel(const float* __restrict__ out_e,
                                                   const float* __restrict__ out_d)
{
    const size_t i = (size_t)blockIdx.x * blockDim.x + threadIdx.x;   // over B*S*(H/4)
    const size_t total = (size_t)BATCH * SRC * (HD / 4);
    if (i >= total) return;

    const int h4 = (int)(i % (HD / 4));
    const size_t bs = i / (HD / 4);
    const int s = (int)(bs % SRC);
    const int b = (int)(bs / SRC);

    const float4* e0 = reinterpret_cast<const float4*>(out_e + ((size_t)s * BATCH + b) * (2 * HD));
    float4 x = e0[h4];
    float4 y = e0[HD / 4 + h4];
    float4 r;
    r.x = x.x + y.x; r.y = x.y + y.y; r.z = x.z + y.z; r.w = x.w + y.w;
    reinterpret_cast<float4*>(g_OE)[i] = r;

    const float4* d0 = reinterpret_cast<const float4*>(out_d + ((size_t)s * BATCH + b) * HD);
    reinterpret_cast<float4*>(g_Q)[i] = d0[h4];
}

// ----------------------------------------------------------------
// gemm_qk (NT): att[b][t][s] = sum_h Q[b][t][h] * OE[b][s][h]
// M = TGT, N = SRC, K = HD.  128x128 tile, BK=8, 8x8 per thread.
// Double-buffered smem pipeline: one __syncthreads per K-step.
// ----------------------------------------------------------------
__global__ __launch_bounds__(256) void gemm_qk_kernel()
{
    const int b = blockIdx.z;
    const float* __restrict__ A  = g_Q  + (size_t)b * TGT * HD;   // [M][K] K-contig
    const float* __restrict__ Bm = g_OE + (size_t)b * SRC * HD;   // [N][K] K-contig
    float* __restrict__ C = g_ATT + (size_t)b * TGT * SRC;        // [M][N]

    __shared__ float As[2][8][128];
    __shared__ float Bs[2][8][128];

    const int tid = threadIdx.x;
    const int tx = tid & 15;          // 0..15 -> N micro
    const int ty = tid >> 4;          // 0..15 -> M micro
    const int rowBase = blockIdx.y * 128;
    const int colBase = blockIdx.x * 128;

    const int lr = tid >> 1;          // 0..127 : row within tile
    const int lk = (tid & 1) * 4;     // 0 or 4 : k-offset

    const float* Aptr = A  + (size_t)(rowBase + lr) * HD + lk;
    const float* Bptr = Bm + (size_t)(colBase + lr) * HD + lk;

    float acc[8][8];
    #pragma unroll
    for (int i = 0; i < 8; ++i)
        #pragma unroll
        for (int j = 0; j < 8; ++j) acc[i][j] = 0.f;

    // preload first tile
    float4 av = *reinterpret_cast<const float4*>(Aptr);
    float4 bv = *reinterpret_cast<const float4*>(Bptr);
    As[0][lk + 0][lr] = av.x; As[0][lk + 1][lr] = av.y;
    As[0][lk + 2][lr] = av.z; As[0][lk + 3][lr] = av.w;
    Bs[0][lk + 0][lr] = bv.x; Bs[0][lk + 1][lr] = bv.y;
    Bs[0][lk + 2][lr] = bv.z; Bs[0][lk + 3][lr] = bv.w;
    __syncthreads();

    int buf = 0;
    for (int k0 = 0; k0 < HD; k0 += 8) {
        const bool hasNext = (k0 + 8) < HD;
        if (hasNext) {
            av = *reinterpret_cast<const float4*>(Aptr + k0 + 8);
            bv = *reinterpret_cast<const float4*>(Bptr + k0 + 8);
        }

        #pragma unroll
        for (int k = 0; k < 8; ++k) {
            float a[8], bb[8];
            #pragma unroll
            for (int i = 0; i < 8; ++i) a[i] = As[buf][k][ty * 8 + i];
            #pragma unroll
            for (int j = 0; j < 8; ++j) bb[j] = Bs[buf][k][tx * 8 + j];
            #pragma unroll
            for (int i = 0; i < 8; ++i)
                #pragma unroll
                for (int j = 0; j < 8; ++j)
                    acc[i][j] = fmaf(a[i], bb[j], acc[i][j]);
        }

        if (hasNext) {
            const int nb = buf ^ 1;
            As[nb][lk + 0][lr] = av.x; As[nb][lk + 1][lr] = av.y;
            As[nb][lk + 2][lr] = av.z; As[nb][lk + 3][lr] = av.w;
            Bs[nb][lk + 0][lr] = bv.x; Bs[nb][lk + 1][lr] = bv.y;
            Bs[nb][lk + 2][lr] = bv.z; Bs[nb][lk + 3][lr] = bv.w;
            __syncthreads();
            buf = nb;
        }
    }

    #pragma unroll
    for (int i = 0; i < 8; ++i) {
        float* crow = C + (size_t)(rowBase + ty * 8 + i) * SRC + colBase + tx * 8;
        float4* c4 = reinterpret_cast<float4*>(crow);
        float4 v0, v1;
        v0.x = acc[i][0]; v0.y = acc[i][1]; v0.z = acc[i][2]; v0.w = acc[i][3];
        v1.x = acc[i][4]; v1.y = acc[i][5]; v1.z = acc[i][6]; v1.w = acc[i][7];
        c4[0] = v0; c4[1] = v1;
    }
}

// ----------------------------------------------------------------
// softmax over s for each (b,t) row: att[b][t][0..SRC)
// one 256-thread block per row; 8 values per thread in registers
// ----------------------------------------------------------------
__global__ __launch_bounds__(256) void softmax_kernel()
{
    float* __restrict__ p = g_ATT + (size_t)blockIdx.x * SRC;
    const int tid = threadIdx.x;

    __shared__ float redm[8];
    __shared__ float reds[8];

    float v[8];
    float m = -INFINITY;
    #pragma unroll
    for (int i = 0; i < 8; ++i) {
        v[i] = p[tid + i * 256];
        m = fmaxf(m, v[i]);
    }
    #pragma unroll
    for (int o = 16; o > 0; o >>= 1) m = fmaxf(m, __shfl_xor_sync(0xffffffffu, m, o));
    if ((tid & 31) == 0) redm[tid >> 5] = m;
    __syncthreads();
    float mAll = redm[0];
    #pragma unroll
    for (int w = 1; w < 8; ++w) mAll = fmaxf(mAll, redm[w]);

    float s = 0.f;
    #pragma unroll
    for (int i = 0; i < 8; ++i) {
        v[i] = __expf(v[i] - mAll);
        s += v[i];
    }
    #pragma unroll
    for (int o = 16; o > 0; o >>= 1) s += __shfl_xor_sync(0xffffffffu, s, o);
    if ((tid & 31) == 0) reds[tid >> 5] = s;
    __syncthreads();
    float sAll = 0.f;
    #pragma unroll
    for (int w = 0; w < 8; ++w) sAll += reds[w];

    const float inv = 1.0f / sAll;
    #pragma unroll
    for (int i = 0; i < 8; ++i) p[tid + i * 256] = v[i] * inv;
}

// ----------------------------------------------------------------
// gemm_pv (NN): out[t][b][h] = sum_s att[b][t][s] * OE[b][s][h]
// M = TGT, N = HD, K = SRC.  128x128 tile, BK=8, 8x8 per thread.
// Double-buffered smem pipeline.
// ----------------------------------------------------------------
__global__ __launch_bounds__(256) void gemm_pv_kernel(float* __restrict__ out)
{
    const int b = blockIdx.z;
    const float* __restrict__ A  = g_ATT + (size_t)b * TGT * SRC;  // [M][K] K-contig
    const float* __restrict__ Bm = g_OE  + (size_t)b * SRC * HD;   // [K][N] N-contig

    __shared__ float As[2][8][128];
    __shared__ float Bs[2][8][128];

    const int tid = threadIdx.x;
    const int tx = tid & 15;
    const int ty = tid >> 4;
    const int rowBase = blockIdx.y * 128;
    const int colBase = blockIdx.x * 128;

    // A tile loader (K-contig rows)
    const int lr = tid >> 1;
    const int lk = (tid & 1) * 4;
    const float* Aptr = A + (size_t)(rowBase + lr) * SRC + lk;

    // B tile loader: [8 x 128], N-contig rows
    const int bkr = tid >> 5;           // 0..7  : k-row
    const int bnc = (tid & 31) * 4;     // 0..124: n-col
    const float* Bptr = Bm + (size_t)bkr * HD + colBase + bnc;

    float acc[8][8];
    #pragma unroll
    for (int i = 0; i < 8; ++i)
        #pragma unroll
        for (int j = 0; j < 8; ++j) acc[i][j] = 0.f;

    // preload first tile
    float4 av = *reinterpret_cast<const float4*>(Aptr);
    float4 bv = *reinterpret_cast<const float4*>(Bptr);
    As[0][lk + 0][lr] = av.x; As[0][lk + 1][lr] = av.y;
    As[0][lk + 2][lr] = av.z; As[0][lk + 3][lr] = av.w;
    *reinterpret_cast<float4*>(&Bs[0][bkr][bnc]) = bv;
    __syncthreads();

    int buf = 0;
    for (int k0 = 0; k0 < SRC; k0 += 8) {
        const bool hasNext = (k0 + 8) < SRC;
        if (hasNext) {
            av = *reinterpret_cast<const float4*>(Aptr + k0 + 8);
            bv = *reinterpret_cast<const float4*>(Bptr + (size_t)(k0 + 8) * HD);
        }

        #pragma unroll
        for (int k = 0; k < 8; ++k) {
            float a[8], bb[8];
            #pragma unroll
            for (int i = 0; i < 8; ++i) a[i] = As[buf][k][ty * 8 + i];
            #pragma unroll
            for (int j = 0; j < 8; ++j) bb[j] = Bs[buf][k][tx * 8 + j];
            #pragma unroll
            for (int i = 0; i < 8; ++i)
                #pragma unroll
                for (int j = 0; j < 8; ++j)
                    acc[i][j] = fmaf(a[i], bb[j], acc[i][j]);
        }

        if (hasNext) {
            const int nb = buf ^ 1;
            As[nb][lk + 0][lr] = av.x; As[nb][lk + 1][lr] = av.y;
            As[nb][lk + 2][lr] = av.z; As[nb][lk + 3][lr] = av.w;
            *reinterpret_cast<float4*>(&Bs[nb][bkr][bnc]) = bv;
            __syncthreads();
            buf = nb;
        }
    }

    // epilogue: out[( t*BATCH + b )*HD + h]
    #pragma unroll
    for (int i = 0; i < 8; ++i) {
        const int t = rowBase + ty * 8 + i;
        float* crow = out + ((size_t)t * BATCH + b) * HD + colBase + tx * 8;
        float4* c4 = reinterpret_cast<float4*>(crow);
        float4 v0, v1;
        v0.x = acc[i][0]; v0.y = acc[i][1]; v0.z = acc[i][2]; v0.w = acc[i][3];
        v1.x = acc[i][4]; v1.y = acc[i][5]; v1.z = acc[i][6]; v1.w = acc[i][7];
        c4[0] = v0; c4[1] = v1;
    }
}

// ----------------------------------------------------------------
extern "C" void kernel_launch(void* const* d_in, const int* in_sizes, int n_in,
                              void* d_out, int out_size)
{
    (void)in_sizes; (void)n_in; (void)out_size;
    const float* out_e = (const float*)d_in[1];   // [SRC][B][2H]
    const float* out_d = (const float*)d_in[2];   // [TGT][B][H]
    float* out = (float*)d_out;                   // [TGT][B][H]

    const int prepTotal = BATCH * SRC * (HD / 4);           // 4,194,304
    prep_kernel<<<prepTotal / 256, 256>>>(out_e, out_d);

    dim3 g1(SRC / 128, TGT / 128, BATCH);                   // 16 x 16 x 16
    gemm_qk_kernel<<<g1, 256>>>();

    softmax_kernel<<<BATCH * TGT, 256>>>();                 // 32768 rows

    dim3 g2(HD / 128, TGT / 128, BATCH);                    // 4 x 16 x 16
    gemm_pv_kernel<<<g2, 256>>>(out);
}

// round 5
// speedup vs baseline: 2.1788x; 2.1788x over previous
#include <cuda_runtime.h>
#include <cuda_bf16.h>
#include <math.h>
#include <stdint.h>

#define SRC   2048
#define TGT   2048
#define BATCH 16
#define HD    512

typedef __nv_bfloat16 bf16;

// -------- scratch (device globals; no runtime allocation) --------
__device__ bf16  g_Qh [(size_t)BATCH * TGT * HD];    // 33.5 MB each
__device__ bf16  g_Ql [(size_t)BATCH * TGT * HD];
__device__ bf16  g_OEh[(size_t)BATCH * SRC * HD];
__device__ bf16  g_OEl[(size_t)BATCH * SRC * HD];
__device__ bf16  g_OETh[(size_t)BATCH * HD * SRC];
__device__ bf16  g_OETl[(size_t)BATCH * HD * SRC];
__device__ float g_ATT[(size_t)BATCH * TGT * SRC];   // 268 MB (fp32 logits)
__device__ bf16  g_Ph [(size_t)BATCH * TGT * SRC];   // 134 MB
__device__ bf16  g_Pl [(size_t)BATCH * TGT * SRC];   // 134 MB

// ================= helpers =================
__device__ __forceinline__ uint32_t smem_u32(const void* p) {
    uint32_t a;
    asm("{ .reg .u64 t; cvta.to.shared.u64 t, %1; cvt.u32.u64 %0, t; }"
        : "=r"(a) : "l"(p));
    return a;
}

#define LDSM4(r, addr)                                                        \
    asm volatile("ldmatrix.sync.aligned.m8n8.x4.shared.b16 {%0,%1,%2,%3}, [%4];" \
                 : "=r"((r)[0]), "=r"((r)[1]), "=r"((r)[2]), "=r"((r)[3])     \
                 : "r"(addr))

#define MMA16816(c, a, b0, b1)                                                \
    asm volatile("mma.sync.aligned.m16n8k16.row.col.f32.bf16.bf16.f32 "       \
                 "{%0,%1,%2,%3},{%4,%5,%6,%7},{%8,%9},{%0,%1,%2,%3};"         \
                 : "+f"((c)[0]), "+f"((c)[1]), "+f"((c)[2]), "+f"((c)[3])     \
                 : "r"((a)[0]), "r"((a)[1]), "r"((a)[2]), "r"((a)[3]),        \
                   "r"(b0), "r"(b1))

#define CP16(dst, src)                                                        \
    asm volatile("cp.async.cg.shared.global [%0], [%1], 16;" :: "r"(dst), "l"(src))
#define CP_COMMIT() asm volatile("cp.async.commit_group;" ::: "memory")
#define CP_WAIT1()  asm volatile("cp.async.wait_group 1;" ::: "memory")
#define CP_WAIT0()  asm volatile("cp.async.wait_group 0;" ::: "memory")

// SMEM: padded rows, stride 40 bf16 (80 B) => conflict-free ldmatrix.
// Per buffer: Ah(10240) Al(10240) Bh(10240) Bl(10240) = 40960 B; x2 buffers = 81920 B
#define TILE_B   10240
#define BUF_B    40960
#define SMEM_GEMM 81920

// async-copy one 128x32 bf16 tile (row stride ld) into smem (stride 40)
__device__ __forceinline__ void tile_cp(const bf16* __restrict__ g, size_t ld, int k0,
                                        uint32_t sbase, int tid) {
    #pragma unroll
    for (int i = 0; i < 2; ++i) {
        int v = i * 256 + tid;          // 0..511
        int row = v >> 2;
        int c = v & 3;
        uint32_t dst = sbase + (uint32_t)(row * 40 + c * 8) * 2u;
        const bf16* src = g + (size_t)row * ld + k0 + c * 8;
        CP16(dst, src);
    }
}

// Mainloop: acc += A(128xK) * B(128xK)^T, split-bf16 3-MMA.
// A rows = M tile (128), B rows = N tile (128), both K-major.
template <int KTOT>
__device__ __forceinline__ void mma_mainloop(const bf16* __restrict__ Ah, const bf16* __restrict__ Al,
                                             size_t lda,
                                             const bf16* __restrict__ Bh, const bf16* __restrict__ Bl,
                                             size_t ldb,
                                             float (&acc)[4][4][4], uint32_t s0, int tid)
{
    const int NC = KTOT / 32;
    const int lane = tid & 31;
    const int wid = tid >> 5;
    const int wm = wid & 1;       // 2 warps over M (64 rows each)
    const int wn = wid >> 1;      // 4 warps over N (32 cols each)

    // ldmatrix lane addressing (element offsets, x2 for bytes)
    const int aRow = wm * 64 + (lane & 15);
    const int aCol = (lane >> 4) << 3;              // 0 or 8
    const int bRow = wn * 32 + (lane & 7) + ((lane >> 4) << 3);
    const int bCol = lane & 8;                      // 0 or 8

    // prefetch chunk 0
    tile_cp(Ah, lda, 0, s0,              tid);
    tile_cp(Al, lda, 0, s0 + TILE_B,     tid);
    tile_cp(Bh, ldb, 0, s0 + 2 * TILE_B, tid);
    tile_cp(Bl, ldb, 0, s0 + 3 * TILE_B, tid);
    CP_COMMIT();

    for (int kc = 0; kc < NC; ++kc) {
        const int cur = kc & 1;
        if (kc + 1 < NC) {
            const int nxt = cur ^ 1;
            const int k0 = (kc + 1) * 32;
            uint32_t nb = s0 + nxt * BUF_B;
            tile_cp(Ah, lda, k0, nb,              tid);
            tile_cp(Al, lda, k0, nb + TILE_B,     tid);
            tile_cp(Bh, ldb, k0, nb + 2 * TILE_B, tid);
            tile_cp(Bl, ldb, k0, nb + 3 * TILE_B, tid);
            CP_COMMIT();
            CP_WAIT1();
        } else {
            CP_WAIT0();
        }
        __syncthreads();

        const uint32_t As_h = s0 + cur * BUF_B;
        const uint32_t As_l = As_h + TILE_B;
        const uint32_t Bs_h = As_h + 2 * TILE_B;
        const uint32_t Bs_l = As_h + 3 * TILE_B;

        #pragma unroll
        for (int k16 = 0; k16 < 2; ++k16) {
            const int kOff = k16 * 16;
            uint32_t a_h[4][4], a_l[4][4];
            uint32_t b_h[2][4], b_l[2][4];

            #pragma unroll
            for (int mi = 0; mi < 4; ++mi) {
                uint32_t off = (uint32_t)((aRow + mi * 16) * 40 + kOff + aCol) * 2u;
                LDSM4(a_h[mi], As_h + off);
                LDSM4(a_l[mi], As_l + off);
            }
            #pragma unroll
            for (int n2 = 0; n2 < 2; ++n2) {
                uint32_t off = (uint32_t)((bRow + n2 * 16) * 40 + kOff + bCol) * 2u;
                LDSM4(b_h[n2], Bs_h + off);
                LDSM4(b_l[n2], Bs_l + off);
            }

            #pragma unroll
            for (int mi = 0; mi < 4; ++mi) {
                #pragma unroll
                for (int ni = 0; ni < 4; ++ni) {
                    const int n2 = ni >> 1;
                    const int sb = (ni & 1) * 2;
                    MMA16816(acc[mi][ni], a_h[mi], b_h[n2][sb], b_h[n2][sb + 1]); // hi*hi
                    MMA16816(acc[mi][ni], a_h[mi], b_l[n2][sb], b_l[n2][sb + 1]); // hi*lo
                    MMA16816(acc[mi][ni], a_l[mi], b_h[n2][sb], b_h[n2][sb + 1]); // lo*hi
                }
            }
        }
        __syncthreads();
    }
}

// ----------------------------------------------------------------
// prep: oe = fwd+bwd half sum -> hi/lo bf16 [B][S][H];  q -> hi/lo bf16 [B][T][H]
// ----------------------------------------------------------------
__global__ __launch_bounds__(256) void prep_kernel(const float* __restrict__ out_e,
                                                   const float* __restrict__ out_d)
{
    const size_t i = (size_t)blockIdx.x * blockDim.x + threadIdx.x;   // B*S*(H/4)
    const size_t total = (size_t)BATCH * SRC * (HD / 4);
    if (i >= total) return;

    const int h4 = (int)(i % (HD / 4));
    const size_t bs = i / (HD / 4);
    const int s = (int)(bs % SRC);
    const int b = (int)(bs / SRC);

    // encoder states
    {
        const float4* e0 = reinterpret_cast<const float4*>(out_e + ((size_t)s * BATCH + b) * (2 * HD));
        float4 x = e0[h4];
        float4 y = e0[HD / 4 + h4];
        float r0 = x.x + y.x, r1 = x.y + y.y, r2 = x.z + y.z, r3 = x.w + y.w;

        __nv_bfloat162 h01 = __floats2bfloat162_rn(r0, r1);
        __nv_bfloat162 h23 = __floats2bfloat162_rn(r2, r3);
        __nv_bfloat162 l01 = __floats2bfloat162_rn(r0 - __low2float(h01), r1 - __high2float(h01));
        __nv_bfloat162 l23 = __floats2bfloat162_rn(r2 - __low2float(h23), r3 - __high2float(h23));
        uint2 uh = make_uint2(reinterpret_cast<uint32_t&>(h01), reinterpret_cast<uint32_t&>(h23));
        uint2 ul = make_uint2(reinterpret_cast<uint32_t&>(l01), reinterpret_cast<uint32_t&>(l23));
        reinterpret_cast<uint2*>(g_OEh)[i] = uh;
        reinterpret_cast<uint2*>(g_OEl)[i] = ul;
    }
    // decoder states
    {
        const float4* d0 = reinterpret_cast<const float4*>(out_d + ((size_t)s * BATCH + b) * HD);
        float4 q = d0[h4];
        __nv_bfloat162 h01 = __floats2bfloat162_rn(q.x, q.y);
        __nv_bfloat162 h23 = __floats2bfloat162_rn(q.z, q.w);
        __nv_bfloat162 l01 = __floats2bfloat162_rn(q.x - __low2float(h01), q.y - __high2float(h01));
        __nv_bfloat162 l23 = __floats2bfloat162_rn(q.z - __low2float(h23), q.w - __high2float(h23));
        uint2 uh = make_uint2(reinterpret_cast<uint32_t&>(h01), reinterpret_cast<uint32_t&>(h23));
        uint2 ul = make_uint2(reinterpret_cast<uint32_t&>(l01), reinterpret_cast<uint32_t&>(l23));
        reinterpret_cast<uint2*>(g_Qh)[i] = uh;
        reinterpret_cast<uint2*>(g_Ql)[i] = ul;
    }
}

// ----------------------------------------------------------------
// transpose hi/lo: OET[b][h][s] = OE[b][s][h]
// ----------------------------------------------------------------
__global__ __launch_bounds__(256) void transpose_kernel()
{
    __shared__ unsigned short th[32][33];
    __shared__ unsigned short tl[32][33];
    const int b  = blockIdx.z;
    const int s0 = blockIdx.x * 32;
    const int h0 = blockIdx.y * 32;
    const unsigned short* sh = reinterpret_cast<const unsigned short*>(g_OEh) + (size_t)b * SRC * HD;
    const unsigned short* sl = reinterpret_cast<const unsigned short*>(g_OEl) + (size_t)b * SRC * HD;
    unsigned short* dh = reinterpret_cast<unsigned short*>(g_OETh) + (size_t)b * HD * SRC;
    unsigned short* dl = reinterpret_cast<unsigned short*>(g_OETl) + (size_t)b * HD * SRC;
    const int x = threadIdx.x;   // 32
    const int y = threadIdx.y;   // 8

    #pragma unroll
    for (int i = 0; i < 32; i += 8) {
        th[y + i][x] = sh[(size_t)(s0 + y + i) * HD + h0 + x];
        tl[y + i][x] = sl[(size_t)(s0 + y + i) * HD + h0 + x];
    }
    __syncthreads();
    #pragma unroll
    for (int i = 0; i < 32; i += 8) {
        dh[(size_t)(h0 + y + i) * SRC + s0 + x] = th[x][y + i];
        dl[(size_t)(h0 + y + i) * SRC + s0 + x] = tl[x][y + i];
    }
}

// ----------------------------------------------------------------
// QK: att[b][t][s] = Q[b][t][:] . OE[b][s][:]  (fp32 logits out)
// ----------------------------------------------------------------
__global__ __launch_bounds__(256, 1) void gemm_qk_mma()
{
    extern __shared__ char smem[];
    const uint32_t s0 = smem_u32(smem);
    const int tid = threadIdx.x;
    const int b = blockIdx.z;
    const int rowBase = blockIdx.y * 128;
    const int colBase = blockIdx.x * 128;

    const bf16* Ah = g_Qh  + ((size_t)b * TGT + rowBase) * HD;
    const bf16* Al = g_Ql  + ((size_t)b * TGT + rowBase) * HD;
    const bf16* Bh = g_OEh + ((size_t)b * SRC + colBase) * HD;
    const bf16* Bl = g_OEl + ((size_t)b * SRC + colBase) * HD;

    float acc[4][4][4];
    #pragma unroll
    for (int i = 0; i < 4; ++i)
        #pragma unroll
        for (int j = 0; j < 4; ++j)
            #pragma unroll
            for (int k = 0; k < 4; ++k) acc[i][j][k] = 0.f;

    mma_mainloop<HD>(Ah, Al, HD, Bh, Bl, HD, acc, s0, tid);

    float* C = g_ATT + (size_t)b * TGT * SRC;
    const int lane = tid & 31, wid = tid >> 5, wm = wid & 1, wn = wid >> 1;
    const int group = lane >> 2, q = lane & 3;
    #pragma unroll
    for (int mi = 0; mi < 4; ++mi) {
        #pragma unroll
        for (int ni = 0; ni < 4; ++ni) {
            const int r0 = rowBase + wm * 64 + mi * 16 + group;
            const int c0 = colBase + wn * 32 + ni * 8 + q * 2;
            *reinterpret_cast<float2*>(C + (size_t)r0 * SRC + c0) =
                make_float2(acc[mi][ni][0], acc[mi][ni][1]);
            *reinterpret_cast<float2*>(C + (size_t)(r0 + 8) * SRC + c0) =
                make_float2(acc[mi][ni][2], acc[mi][ni][3]);
        }
    }
}

// ----------------------------------------------------------------
// softmax over s, writes split-bf16 P
// ----------------------------------------------------------------
__global__ __launch_bounds__(256) void softmax_split_kernel()
{
    const size_t row = blockIdx.x;
    const float* __restrict__ p = g_ATT + row * SRC;
    bf16* __restrict__ ph = g_Ph + row * SRC;
    bf16* __restrict__ pl = g_Pl + row * SRC;
    const int tid = threadIdx.x;

    __shared__ float redm[8];
    __shared__ float reds[8];

    float v[8];
    float m = -INFINITY;
    #pragma unroll
    for (int i = 0; i < 8; ++i) {
        v[i] = p[tid + i * 256];
        m = fmaxf(m, v[i]);
    }
    #pragma unroll
    for (int o = 16; o > 0; o >>= 1) m = fmaxf(m, __shfl_xor_sync(0xffffffffu, m, o));
    if ((tid & 31) == 0) redm[tid >> 5] = m;
    __syncthreads();
    float mAll = redm[0];
    #pragma unroll
    for (int w = 1; w < 8; ++w) mAll = fmaxf(mAll, redm[w]);

    float s = 0.f;
    #pragma unroll
    for (int i = 0; i < 8; ++i) {
        v[i] = __expf(v[i] - mAll);
        s += v[i];
    }
    #pragma unroll
    for (int o = 16; o > 0; o >>= 1) s += __shfl_xor_sync(0xffffffffu, s, o);
    if ((tid & 31) == 0) reds[tid >> 5] = s;
    __syncthreads();
    float sAll = 0.f;
    #pragma unroll
    for (int w = 0; w < 8; ++w) sAll += reds[w];

    const float inv = 1.0f / sAll;
    #pragma unroll
    for (int i = 0; i < 8; ++i) {
        float pv = v[i] * inv;
        bf16 hi = __float2bfloat16_rn(pv);
        bf16 lo = __float2bfloat16_rn(pv - __bfloat162float(hi));
        ph[tid + i * 256] = hi;
        pl[tid + i * 256] = lo;
    }
}

// ----------------------------------------------------------------
// PV: out[t][b][h] = sum_s P[b][t][s] * OET[b][h][s]
// ----------------------------------------------------------------
__global__ __launch_bounds__(256, 1) void gemm_pv_mma(float* __restrict__ out)
{
    extern __shared__ char smem[];
    const uint32_t s0 = smem_u32(smem);
    const int tid = threadIdx.x;
    const int b = blockIdx.z;
    const int rowBase = blockIdx.y * 128;   // t
    const int colBase = blockIdx.x * 128;   // h

    const bf16* Ah = g_Ph   + ((size_t)b * TGT + rowBase) * SRC;
    const bf16* Al = g_Pl   + ((size_t)b * TGT + rowBase) * SRC;
    const bf16* Bh = g_OETh + ((size_t)b * HD + colBase) * SRC;
    const bf16* Bl = g_OETl + ((size_t)b * HD + colBase) * SRC;

    float acc[4][4][4];
    #pragma unroll
    for (int i = 0; i < 4; ++i)
        #pragma unroll
        for (int j = 0; j < 4; ++j)
            #pragma unroll
            for (int k = 0; k < 4; ++k) acc[i][j][k] = 0.f;

    mma_mainloop<SRC>(Ah, Al, SRC, Bh, Bl, SRC, acc, s0, tid);

    const int lane = tid & 31, wid = tid >> 5, wm = wid & 1, wn = wid >> 1;
    const int group = lane >> 2, q = lane & 3;
    #pragma unroll
    for (int mi = 0; mi < 4; ++mi) {
        #pragma unroll
        for (int ni = 0; ni < 4; ++ni) {
            const int t0 = rowBase + wm * 64 + mi * 16 + group;
            const int c0 = colBase + wn * 32 + ni * 8 + q * 2;
            *reinterpret_cast<float2*>(out + ((size_t)t0 * BATCH + b) * HD + c0) =
                make_float2(acc[mi][ni][0], acc[mi][ni][1]);
            *reinterpret_cast<float2*>(out + ((size_t)(t0 + 8) * BATCH + b) * HD + c0) =
                make_float2(acc[mi][ni][2], acc[mi][ni][3]);
        }
    }
}

// ----------------------------------------------------------------
extern "C" void kernel_launch(void* const* d_in, const int* in_sizes, int n_in,
                              void* d_out, int out_size)
{
    (void)in_sizes; (void)n_in; (void)out_size;
    const float* out_e = (const float*)d_in[1];   // [SRC][B][2H]
    const float* out_d = (const float*)d_in[2];   // [TGT][B][H]
    float* out = (float*)d_out;                   // [TGT][B][H]

    cudaFuncSetAttribute(gemm_qk_mma, cudaFuncAttributeMaxDynamicSharedMemorySize, SMEM_GEMM);
    cudaFuncSetAttribute(gemm_pv_mma, cudaFuncAttributeMaxDynamicSharedMemorySize, SMEM_GEMM);

    const int prepTotal = BATCH * SRC * (HD / 4);
    prep_kernel<<<prepTotal / 256, 256>>>(out_e, out_d);

    dim3 gt(SRC / 32, HD / 32, BATCH);
    transpose_kernel<<<gt, dim3(32, 8)>>>();

    dim3 g1(SRC / 128, TGT / 128, BATCH);                  // 16 x 16 x 16
    gemm_qk_mma<<<g1, 256, SMEM_GEMM>>>();

    softmax_split_kernel<<<BATCH * TGT, 256>>>();

    dim3 g2(HD / 128, TGT / 128, BATCH);                   // 4 x 16 x 16
    gemm_pv_mma<<<g2, 256, SMEM_GEMM>>>(out);
}

// round 7
// speedup vs baseline: 2.2890x; 1.0506x over previous
#include <cuda_runtime.h>
#include <cuda_bf16.h>
#include <math.h>
#include <stdint.h>

#define SRC   2048
#define TGT   2048
#define BATCH 16
#define HD    512

typedef __nv_bfloat16 bf16;

// -------- scratch (device globals; no runtime allocation) --------
__device__ bf16  g_Qh [(size_t)BATCH * TGT * HD];
__device__ bf16  g_Ql [(size_t)BATCH * TGT * HD];
__device__ bf16  g_OEh[(size_t)BATCH * SRC * HD];
__device__ bf16  g_OEl[(size_t)BATCH * SRC * HD];
__device__ bf16  g_OETh[(size_t)BATCH * HD * SRC];
__device__ bf16  g_OETl[(size_t)BATCH * HD * SRC];
__device__ float g_ATT[(size_t)BATCH * TGT * SRC];   // fp32 logits
__device__ bf16  g_Ph [(size_t)BATCH * TGT * SRC];
__device__ bf16  g_Pl [(size_t)BATCH * TGT * SRC];

// ================= helpers =================
__device__ __forceinline__ uint32_t smem_u32(const void* p) {
    uint32_t a;
    asm("{ .reg .u64 t; cvta.to.shared.u64 t, %1; cvt.u32.u64 %0, t; }"
        : "=r"(a) : "l"(p));
    return a;
}

#define LDSM4(r, addr)                                                        \
    asm volatile("ldmatrix.sync.aligned.m8n8.x4.shared.b16 {%0,%1,%2,%3}, [%4];" \
                 : "=r"((r)[0]), "=r"((r)[1]), "=r"((r)[2]), "=r"((r)[3])     \
                 : "r"(addr))

#define MMA16816(c, a, b0, b1)                                                \
    asm volatile("mma.sync.aligned.m16n8k16.row.col.f32.bf16.bf16.f32 "       \
                 "{%0,%1,%2,%3},{%4,%5,%6,%7},{%8,%9},{%0,%1,%2,%3};"         \
                 : "+f"((c)[0]), "+f"((c)[1]), "+f"((c)[2]), "+f"((c)[3])     \
                 : "r"((a)[0]), "r"((a)[1]), "r"((a)[2]), "r"((a)[3]),        \
                   "r"(b0), "r"(b1))

#define CP16(dst, src)                                                        \
    asm volatile("cp.async.cg.shared.global [%0], [%1], 16;" :: "r"(dst), "l"(src))
#define CP_COMMIT() asm volatile("cp.async.commit_group;" ::: "memory")
#define CP_WAIT1()  asm volatile("cp.async.wait_group 1;" ::: "memory")

// SMEM per stage (padded stride 40 bf16 = 80 B rows, conflict-free ldmatrix):
//   Ah 128x40x2 = 10240 | Al 10240 | Bh 256x40x2 = 20480 | Bl 20480  => 61440
#define A_TILE_B 10240
#define B_TILE_B 20480
#define OFF_AL   10240
#define OFF_BH   20480
#define OFF_BL   40960
#define STAGE_B  61440
#define NSTAGE   3
#define SMEM_GEMM (STAGE_B * NSTAGE)   // 184320

// async-copy 128x32 bf16 (row stride ld) -> smem stride 40 ; 2 CP16/thread
__device__ __forceinline__ void cpA(const bf16* __restrict__ g, size_t ld, int k0,
                                    uint32_t sbase, int tid) {
    #pragma unroll
    for (int i = 0; i < 2; ++i) {
        int v = i * 256 + tid;           // 0..511
        int row = v >> 2;
        int c = v & 3;
        CP16(sbase + (uint32_t)(row * 40 + c * 8) * 2u, g + (size_t)row * ld + k0 + c * 8);
    }
}
// async-copy 256x32 bf16 ; 4 CP16/thread
__device__ __forceinline__ void cpB(const bf16* __restrict__ g, size_t ld, int k0,
                                    uint32_t sbase, int tid) {
    #pragma unroll
    for (int i = 0; i < 4; ++i) {
        int v = i * 256 + tid;           // 0..1023
        int row = v >> 2;
        int c = v & 3;
        CP16(sbase + (uint32_t)(row * 40 + c * 8) * 2u, g + (size_t)row * ld + k0 + c * 8);
    }
}

// Mainloop: acc(64x64 per warp) += A(128xK) * B(256xK)^T, split-bf16 3-MMA.
template <int KTOT>
__device__ __forceinline__ void mma_mainloop(const bf16* __restrict__ Ah, const bf16* __restrict__ Al,
                                             size_t lda,
                                             const bf16* __restrict__ Bh, const bf16* __restrict__ Bl,
                                             size_t ldb,
                                             float (&acc)[4][8][4], uint32_t s0, int tid)
{
    const int NC = KTOT / 32;
    const int lane = tid & 31;
    const int wid = tid >> 5;
    const int wm = wid & 1;       // 2 warps over M (64 rows each)
    const int wn = wid >> 1;      // 4 warps over N (64 cols each)

    const int aRow = wm * 64 + (lane & 15);
    const int aCol = (lane >> 4) << 3;
    const int bRow = wn * 64 + (lane & 7) + ((lane >> 4) << 3);
    const int bCol = lane & 8;

    // prologue: prefetch chunks 0,1
    #pragma unroll
    for (int p = 0; p < 2; ++p) {
        uint32_t sb = s0 + p * STAGE_B;
        cpA(Ah, lda, p * 32, sb,          tid);
        cpA(Al, lda, p * 32, sb + OFF_AL, tid);
        cpB(Bh, ldb, p * 32, sb + OFF_BH, tid);
        cpB(Bl, ldb, p * 32, sb + OFF_BL, tid);
        CP_COMMIT();
    }

    for (int kc = 0; kc < NC; ++kc) {
        CP_WAIT1();                      // chunk kc resident
        __syncthreads();                 // all warps done with the stage we overwrite

        // prefetch chunk kc+2 (empty commit on tail keeps group ledger aligned)
        if (kc + 2 < NC) {
            uint32_t sb = s0 + ((kc + 2) % NSTAGE) * STAGE_B;
            const int k0 = (kc + 2) * 32;
            cpA(Ah, lda, k0, sb,          tid);
            cpA(Al, lda, k0, sb + OFF_AL, tid);
            cpB(Bh, ldb, k0, sb + OFF_BH, tid);
            cpB(Bl, ldb, k0, sb + OFF_BL, tid);
        }
        CP_COMMIT();

        const uint32_t st = s0 + (kc % NSTAGE) * STAGE_B;
        const uint32_t As_h = st, As_l = st + OFF_AL;
        const uint32_t Bs_h = st + OFF_BH, Bs_l = st + OFF_BL;

        #pragma unroll
        for (int k16 = 0; k16 < 2; ++k16) {
            const int kOff = k16 * 16;
            uint32_t a_h[4][4], a_l[4][4];
            uint32_t b_h[4][4], b_l[4][4];

            #pragma unroll
            for (int mi = 0; mi < 4; ++mi) {
                uint32_t off = (uint32_t)((aRow + mi * 16) * 40 + kOff + aCol) * 2u;
                LDSM4(a_h[mi], As_h + off);
                LDSM4(a_l[mi], As_l + off);
            }
            #pragma unroll
            for (int n2 = 0; n2 < 4; ++n2) {
                uint32_t off = (uint32_t)((bRow + n2 * 16) * 40 + kOff + bCol) * 2u;
                LDSM4(b_h[n2], Bs_h + off);
                LDSM4(b_l[n2], Bs_l + off);
            }

            #pragma unroll
            for (int mi = 0; mi < 4; ++mi) {
                #pragma unroll
                for (int ni = 0; ni < 8; ++ni) {
                    const int n2 = ni >> 1;
                    const int sb = (ni & 1) * 2;
                    MMA16816(acc[mi][ni], a_h[mi], b_h[n2][sb], b_h[n2][sb + 1]); // hi*hi
                    MMA16816(acc[mi][ni], a_h[mi], b_l[n2][sb], b_l[n2][sb + 1]); // hi*lo
                    MMA16816(acc[mi][ni], a_l[mi], b_h[n2][sb], b_h[n2][sb + 1]); // lo*hi
                }
            }
        }
    }
    __syncthreads();
}

// ----------------------------------------------------------------
// prep: oe = fwd+bwd half sum -> hi/lo bf16 [B][S][H];  q -> hi/lo bf16 [B][T][H]
// ----------------------------------------------------------------
__global__ __launch_bounds__(256) void prep_kernel(const float* __restrict__ out_e,
                                                   const float* __restrict__ out_d)
{
    const size_t i = (size_t)blockIdx.x * blockDim.x + threadIdx.x;   // B*S*(H/4)
    const size_t total = (size_t)BATCH * SRC * (HD / 4);
    if (i >= total) return;

    const int h4 = (int)(i % (HD / 4));
    const size_t bs = i / (HD / 4);
    const int s = (int)(bs % SRC);
    const int b = (int)(bs / SRC);

    {
        const float4* e0 = reinterpret_cast<const float4*>(out_e + ((size_t)s * BATCH + b) * (2 * HD));
        float4 x = e0[h4];
        float4 y = e0[HD / 4 + h4];
        float r0 = x.x + y.x, r1 = x.y + y.y, r2 = x.z + y.z, r3 = x.w + y.w;

        __nv_bfloat162 h01 = __floats2bfloat162_rn(r0, r1);
        __nv_bfloat162 h23 = __floats2bfloat162_rn(r2, r3);
        __nv_bfloat162 l01 = __floats2bfloat162_rn(r0 - __low2float(h01), r1 - __high2float(h01));
        __nv_bfloat162 l23 = __floats2bfloat162_rn(r2 - __low2float(h23), r3 - __high2float(h23));
        uint2 uh = make_uint2(reinterpret_cast<uint32_t&>(h01), reinterpret_cast<uint32_t&>(h23));
        uint2 ul = make_uint2(reinterpret_cast<uint32_t&>(l01), reinterpret_cast<uint32_t&>(l23));
        reinterpret_cast<uint2*>(g_OEh)[i] = uh;
        reinterpret_cast<uint2*>(g_OEl)[i] = ul;
    }
    {
        const float4* d0 = reinterpret_cast<const float4*>(out_d + ((size_t)s * BATCH + b) * HD);
        float4 q = d0[h4];
        __nv_bfloat162 h01 = __floats2bfloat162_rn(q.x, q.y);
        __nv_bfloat162 h23 = __floats2bfloat162_rn(q.z, q.w);
        __nv_bfloat162 l01 = __floats2bfloat162_rn(q.x - __low2float(h01), q.y - __high2float(h01));
        __nv_bfloat162 l23 = __floats2bfloat162_rn(q.z - __low2float(h23), q.w - __high2float(h23));
        uint2 uh = make_uint2(reinterpret_cast<uint32_t&>(h01), reinterpret_cast<uint32_t&>(h23));
        uint2 ul = make_uint2(reinterpret_cast<uint32_t&>(l01), reinterpret_cast<uint32_t&>(l23));
        reinterpret_cast<uint2*>(g_Qh)[i] = uh;
        reinterpret_cast<uint2*>(g_Ql)[i] = ul;
    }
}

// ----------------------------------------------------------------
// transpose hi/lo: OET[b][h][s] = OE[b][s][h]
// ----------------------------------------------------------------
__global__ __launch_bounds__(256) void transpose_kernel()
{
    __shared__ unsigned short th[32][33];
    __shared__ unsigned short tl[32][33];
    const int b  = blockIdx.z;
    const int s0 = blockIdx.x * 32;
    const int h0 = blockIdx.y * 32;
    const unsigned short* sh = reinterpret_cast<const unsigned short*>(g_OEh) + (size_t)b * SRC * HD;
    const unsigned short* sl = reinterpret_cast<const unsigned short*>(g_OEl) + (size_t)b * SRC * HD;
    unsigned short* dh = reinterpret_cast<unsigned short*>(g_OETh) + (size_t)b * HD * SRC;
    unsigned short* dl = reinterpret_cast<unsigned short*>(g_OETl) + (size_t)b * HD * SRC;
    const int x = threadIdx.x;
    const int y = threadIdx.y;

    #pragma unroll
    for (int i = 0; i < 32; i += 8) {
        th[y + i][x] = sh[(size_t)(s0 + y + i) * HD + h0 + x];
        tl[y + i][x] = sl[(size_t)(s0 + y + i) * HD + h0 + x];
    }
    __syncthreads();
    #pragma unroll
    for (int i = 0; i < 32; i += 8) {
        dh[(size_t)(h0 + y + i) * SRC + s0 + x] = th[x][y + i];
        dl[(size_t)(h0 + y + i) * SRC + s0 + x] = tl[x][y + i];
    }
}

// ----------------------------------------------------------------
// QK: att[b][t][s] = Q[b][t][:] . OE[b][s][:]  (fp32 logits)
// CTA tile 128(t) x 256(s)
// ----------------------------------------------------------------
__global__ __launch_bounds__(256, 1) void gemm_qk_mma()
{
    extern __shared__ char smem[];
    const uint32_t s0 = smem_u32(smem);
    const int tid = threadIdx.x;
    const int b = blockIdx.z;
    const int rowBase = blockIdx.y * 128;
    const int colBase = blockIdx.x * 256;

    const bf16* Ah = g_Qh  + ((size_t)b * TGT + rowBase) * HD;
    const bf16* Al = g_Ql  + ((size_t)b * TGT + rowBase) * HD;
    const bf16* Bh = g_OEh + ((size_t)b * SRC + colBase) * HD;
    const bf16* Bl = g_OEl + ((size_t)b * SRC + colBase) * HD;

    float acc[4][8][4];
    #pragma unroll
    for (int i = 0; i < 4; ++i)
        #pragma unroll
        for (int j = 0; j < 8; ++j)
            #pragma unroll
            for (int k = 0; k < 4; ++k) acc[i][j][k] = 0.f;

    mma_mainloop<HD>(Ah, Al, HD, Bh, Bl, HD, acc, s0, tid);

    float* C = g_ATT + (size_t)b * TGT * SRC;
    const int lane = tid & 31, wid = tid >> 5, wm = wid & 1, wn = wid >> 1;
    const int group = lane >> 2, q = lane & 3;
    #pragma unroll
    for (int mi = 0; mi < 4; ++mi) {
        #pragma unroll
        for (int ni = 0; ni < 8; ++ni) {
            const int r0 = rowBase + wm * 64 + mi * 16 + group;
            const int c0 = colBase + wn * 64 + ni * 8 + q * 2;
            *reinterpret_cast<float2*>(C + (size_t)r0 * SRC + c0) =
                make_float2(acc[mi][ni][0], acc[mi][ni][1]);
            *reinterpret_cast<float2*>(C + (size_t)(r0 + 8) * SRC + c0) =
                make_float2(acc[mi][ni][2], acc[mi][ni][3]);
        }
    }
}

// ----------------------------------------------------------------
// softmax over s, writes split-bf16 P
// ----------------------------------------------------------------
__global__ __launch_bounds__(256) void softmax_split_kernel()
{
    const size_t row = blockIdx.x;
    const float* __restrict__ p = g_ATT + row * SRC;
    bf16* __restrict__ ph = g_Ph + row * SRC;
    bf16* __restrict__ pl = g_Pl + row * SRC;
    const int tid = threadIdx.x;

    __shared__ float redm[8];
    __shared__ float reds[8];

    float v[8];
    float m = -INFINITY;
    #pragma unroll
    for (int i = 0; i < 8; ++i) {
        v[i] = p[tid + i * 256];
        m = fmaxf(m, v[i]);
    }
    #pragma unroll
    for (int o = 16; o > 0; o >>= 1) m = fmaxf(m, __shfl_xor_sync(0xffffffffu, m, o));
    if ((tid & 31) == 0) redm[tid >> 5] = m;
    __syncthreads();
    float mAll = redm[0];
    #pragma unroll
    for (int w = 1; w < 8; ++w) mAll = fmaxf(mAll, redm[w]);

    float s = 0.f;
    #pragma unroll
    for (int i = 0; i < 8; ++i) {
        v[i] = __expf(v[i] - mAll);
        s += v[i];
    }
    #pragma unroll
    for (int o = 16; o > 0; o >>= 1) s += __shfl_xor_sync(0xffffffffu, s, o);
    if ((tid & 31) == 0) reds[tid >> 5] = s;
    __syncthreads();
    float sAll = 0.f;
    #pragma unroll
    for (int w = 0; w < 8; ++w) sAll += reds[w];

    const float inv = 1.0f / sAll;
    #pragma unroll
    for (int i = 0; i < 8; ++i) {
        float pv = v[i] * inv;
        bf16 hi = __float2bfloat16_rn(pv);
        bf16 lo = __float2bfloat16_rn(pv - __bfloat162float(hi));
        ph[tid + i * 256] = hi;
        pl[tid + i * 256] = lo;
    }
}

// ----------------------------------------------------------------
// PV: out[t][b][h] = sum_s P[b][t][s] * OET[b][h][s]
// CTA tile 128(t) x 256(h)
// ----------------------------------------------------------------
__global__ __launch_bounds__(256, 1) void gemm_pv_mma(float* __restrict__ out)
{
    extern __shared__ char smem[];
    const uint32_t s0 = smem_u32(smem);
    const int tid = threadIdx.x;
    const int b = blockIdx.z;
    const int rowBase = blockIdx.y * 128;   // t
    const int colBase = blockIdx.x * 256;   // h

    const bf16* Ah = g_Ph   + ((size_t)b * TGT + rowBase) * SRC;
    const bf16* Al = g_Pl   + ((size_t)b * TGT + rowBase) * SRC;
    const bf16* Bh = g_OETh + ((size_t)b * HD + colBase) * SRC;
    const bf16* Bl = g_OETl + ((size_t)b * HD + colBase) * SRC;

    float acc[4][8][4];
    #pragma unroll
    for (int i = 0; i < 4; ++i)
        #pragma unroll
        for (int j = 0; j < 8; ++j)
            #pragma unroll
            for (int k = 0; k < 4; ++k) acc[i][j][k] = 0.f;

    mma_mainloop<SRC>(Ah, Al, SRC, Bh, Bl, SRC, acc, s0, tid);

    const int lane = tid & 31, wid = tid >> 5, wm = wid & 1, wn = wid >> 1;
    const int group = lane >> 2, q = lane & 3;
    #pragma unroll
    for (int mi = 0; mi < 4; ++mi) {
        #pragma unroll
        for (int ni = 0; ni < 8; ++ni) {
            const int t0 = rowBase + wm * 64 + mi * 16 + group;
            const int c0 = colBase + wn * 64 + ni * 8 + q * 2;
            *reinterpret_cast<float2*>(out + ((size_t)t0 * BATCH + b) * HD + c0) =
                make_float2(acc[mi][ni][0], acc[mi][ni][1]);
            *reinterpret_cast<float2*>(out + ((size_t)(t0 + 8) * BATCH + b) * HD + c0) =
                make_float2(acc[mi][ni][2], acc[mi][ni][3]);
        }
    }
}

// ----------------------------------------------------------------
extern "C" void kernel_launch(void* const* d_in, const int* in_sizes, int n_in,
                              void* d_out, int out_size)
{
    (void)in_sizes; (void)n_in; (void)out_size;
    const float* out_e = (const float*)d_in[1];   // [SRC][B][2H]
    const float* out_d = (const float*)d_in[2];   // [TGT][B][H]
    float* out = (float*)d_out;                   // [TGT][B][H]

    cudaFuncSetAttribute(gemm_qk_mma, cudaFuncAttributeMaxDynamicSharedMemorySize, SMEM_GEMM);
    cudaFuncSetAttribute(gemm_pv_mma, cudaFuncAttributeMaxDynamicSharedMemorySize, SMEM_GEMM);

    const int prepTotal = BATCH * SRC * (HD / 4);
    prep_kernel<<<prepTotal / 256, 256>>>(out_e, out_d);

    dim3 gt(SRC / 32, HD / 32, BATCH);
    transpose_kernel<<<gt, dim3(32, 8)>>>();

    dim3 g1(SRC / 256, TGT / 128, BATCH);                  // 8 x 16 x 16
    gemm_qk_mma<<<g1, 256, SMEM_GEMM>>>();

    softmax_split_kernel<<<BATCH * TGT, 256>>>();

    dim3 g2(HD / 256, TGT / 128, BATCH);                   // 2 x 16 x 16
    gemm_pv_mma<<<g2, 256, SMEM_GEMM>>>(out);
}

// round 8
// speedup vs baseline: 2.3021x; 1.0057x over previous
#include <cuda_runtime.h>
#include <cuda_bf16.h>
#include <math.h>
#include <stdint.h>

#define SRC   2048
#define TGT   2048
#define BATCH 16
#define HD    512

typedef __nv_bfloat16 bf16;

// -------- scratch (device globals; no runtime allocation) --------
__device__ bf16  g_Qh [(size_t)BATCH * TGT * HD];
__device__ bf16  g_Ql [(size_t)BATCH * TGT * HD];
__device__ bf16  g_OEh[(size_t)BATCH * SRC * HD];
__device__ bf16  g_OEl[(size_t)BATCH * SRC * HD];
__device__ bf16  g_OETh[(size_t)BATCH * HD * SRC];
__device__ bf16  g_OETl[(size_t)BATCH * HD * SRC];
__device__ float g_ATT[(size_t)BATCH * TGT * SRC];   // fp32 logits
__device__ bf16  g_Ph [(size_t)BATCH * TGT * SRC];
__device__ bf16  g_Pl [(size_t)BATCH * TGT * SRC];

// ================= helpers =================
__device__ __forceinline__ uint32_t smem_u32(const void* p) {
    uint32_t a;
    asm("{ .reg .u64 t; cvta.to.shared.u64 t, %1; cvt.u32.u64 %0, t; }"
        : "=r"(a) : "l"(p));
    return a;
}

#define LDSM4(r, addr)                                                        \
    asm volatile("ldmatrix.sync.aligned.m8n8.x4.shared.b16 {%0,%1,%2,%3}, [%4];" \
                 : "=r"((r)[0]), "=r"((r)[1]), "=r"((r)[2]), "=r"((r)[3])     \
                 : "r"(addr))

#define MMA16816(c, a, b0, b1)                                                \
    asm volatile("mma.sync.aligned.m16n8k16.row.col.f32.bf16.bf16.f32 "       \
                 "{%0,%1,%2,%3},{%4,%5,%6,%7},{%8,%9},{%0,%1,%2,%3};"         \
                 : "+f"((c)[0]), "+f"((c)[1]), "+f"((c)[2]), "+f"((c)[3])     \
                 : "r"((a)[0]), "r"((a)[1]), "r"((a)[2]), "r"((a)[3]),        \
                   "r"(b0), "r"(b1))

#define CP16(dst, src)                                                        \
    asm volatile("cp.async.cg.shared.global [%0], [%1], 16;" :: "r"(dst), "l"(src))
#define CP_COMMIT() asm volatile("cp.async.commit_group;" ::: "memory")
#define CP_WAIT1()  asm volatile("cp.async.wait_group 1;" ::: "memory")

// SMEM per stage (padded stride 40 bf16 = 80 B rows, conflict-free ldmatrix):
//   Ah 128x40x2 = 10240 | Al 10240 | Bh 256x40x2 = 20480 | Bl 20480  => 61440
#define OFF_AL   10240
#define OFF_BH   20480
#define OFF_BL   40960
#define STAGE_B  61440
#define NSTAGE   3
#define SMEM_GEMM (STAGE_B * NSTAGE)   // 184320

// async-copy 128x32 bf16 (row stride ld) -> smem stride 40 ; 2 CP16/thread
__device__ __forceinline__ void cpA(const bf16* __restrict__ g, size_t ld, int k0,
                                    uint32_t sbase, int tid) {
    #pragma unroll
    for (int i = 0; i < 2; ++i) {
        int v = i * 256 + tid;           // 0..511
        int row = v >> 2;
        int c = v & 3;
        CP16(sbase + (uint32_t)(row * 40 + c * 8) * 2u, g + (size_t)row * ld + k0 + c * 8);
    }
}
// async-copy 256x32 bf16 ; 4 CP16/thread
__device__ __forceinline__ void cpB(const bf16* __restrict__ g, size_t ld, int k0,
                                    uint32_t sbase, int tid) {
    #pragma unroll
    for (int i = 0; i < 4; ++i) {
        int v = i * 256 + tid;           // 0..1023
        int row = v >> 2;
        int c = v & 3;
        CP16(sbase + (uint32_t)(row * 40 + c * 8) * 2u, g + (size_t)row * ld + k0 + c * 8);
    }
}

// Mainloop: acc(64x64 per warp) += A(128xK) * B(256xK)^T, split-bf16 3-MMA.
// Register discipline: A frags resident (32 regs), B frags loaded per-n2 and
// consumed immediately (8 regs live) => peak ~185 regs, no spills.
template <int KTOT>
__device__ __forceinline__ void mma_mainloop(const bf16* __restrict__ Ah, const bf16* __restrict__ Al,
                                             size_t lda,
                                             const bf16* __restrict__ Bh, const bf16* __restrict__ Bl,
                                             size_t ldb,
                                             float (&acc)[4][8][4], uint32_t s0, int tid)
{
    const int NC = KTOT / 32;
    const int lane = tid & 31;
    const int wid = tid >> 5;
    const int wm = wid & 1;       // 2 warps over M (64 rows each)
    const int wn = wid >> 1;      // 4 warps over N (64 cols each)

    const int aRow = wm * 64 + (lane & 15);
    const int aCol = (lane >> 4) << 3;
    const int bRow = wn * 64 + (lane & 7) + ((lane >> 4) << 3);
    const int bCol = lane & 8;

    // prologue: prefetch chunks 0,1
    #pragma unroll
    for (int p = 0; p < 2; ++p) {
        uint32_t sb = s0 + p * STAGE_B;
        cpA(Ah, lda, p * 32, sb,          tid);
        cpA(Al, lda, p * 32, sb + OFF_AL, tid);
        cpB(Bh, ldb, p * 32, sb + OFF_BH, tid);
        cpB(Bl, ldb, p * 32, sb + OFF_BL, tid);
        CP_COMMIT();
    }

    for (int kc = 0; kc < NC; ++kc) {
        CP_WAIT1();                      // chunk kc resident
        __syncthreads();                 // all warps done with the stage we overwrite

        // prefetch chunk kc+2 (empty commit on tail keeps group ledger aligned)
        if (kc + 2 < NC) {
            uint32_t sb = s0 + ((kc + 2) % NSTAGE) * STAGE_B;
            const int k0 = (kc + 2) * 32;
            cpA(Ah, lda, k0, sb,          tid);
            cpA(Al, lda, k0, sb + OFF_AL, tid);
            cpB(Bh, ldb, k0, sb + OFF_BH, tid);
            cpB(Bl, ldb, k0, sb + OFF_BL, tid);
        }
        CP_COMMIT();

        const uint32_t st = s0 + (kc % NSTAGE) * STAGE_B;
        const uint32_t As_h = st, As_l = st + OFF_AL;
        const uint32_t Bs_h = st + OFF_BH, Bs_l = st + OFF_BL;

        #pragma unroll
        for (int k16 = 0; k16 < 2; ++k16) {
            const int kOff = k16 * 16;
            uint32_t a_h[4][4], a_l[4][4];

            #pragma unroll
            for (int mi = 0; mi < 4; ++mi) {
                uint32_t off = (uint32_t)((aRow + mi * 16) * 40 + kOff + aCol) * 2u;
                LDSM4(a_h[mi], As_h + off);
                LDSM4(a_l[mi], As_l + off);
            }
            #pragma unroll
            for (int n2 = 0; n2 < 4; ++n2) {
                uint32_t b_h[4], b_l[4];
                uint32_t off = (uint32_t)((bRow + n2 * 16) * 40 + kOff + bCol) * 2u;
                LDSM4(b_h, Bs_h + off);
                LDSM4(b_l, Bs_l + off);

                #pragma unroll
                for (int half = 0; half < 2; ++half) {
                    const int ni = n2 * 2 + half;
                    const int sb = half * 2;
                    #pragma unroll
                    for (int mi = 0; mi < 4; ++mi) {
                        MMA16816(acc[mi][ni], a_h[mi], b_h[sb], b_h[sb + 1]); // hi*hi
                        MMA16816(acc[mi][ni], a_h[mi], b_l[sb], b_l[sb + 1]); // hi*lo
                        MMA16816(acc[mi][ni], a_l[mi], b_h[sb], b_h[sb + 1]); // lo*hi
                    }
                }
            }
        }
    }
    __syncthreads();
}

// ----------------------------------------------------------------
// prep: oe = fwd+bwd half sum -> hi/lo bf16 [B][S][H];  q -> hi/lo bf16 [B][T][H]
// ----------------------------------------------------------------
__global__ __launch_bounds__(256) void prep_kernel(const float* __restrict__ out_e,
                                                   const float* __restrict__ out_d)
{
    const size_t i = (size_t)blockIdx.x * blockDim.x + threadIdx.x;   // B*S*(H/4)
    const size_t total = (size_t)BATCH * SRC * (HD / 4);
    if (i >= total) return;

    const int h4 = (int)(i % (HD / 4));
    const size_t bs = i / (HD / 4);
    const int s = (int)(bs % SRC);
    const int b = (int)(bs / SRC);

    {
        const float4* e0 = reinterpret_cast<const float4*>(out_e + ((size_t)s * BATCH + b) * (2 * HD));
        float4 x = e0[h4];
        float4 y = e0[HD / 4 + h4];
        float r0 = x.x + y.x, r1 = x.y + y.y, r2 = x.z + y.z, r3 = x.w + y.w;

        __nv_bfloat162 h01 = __floats2bfloat162_rn(r0, r1);
        __nv_bfloat162 h23 = __floats2bfloat162_rn(r2, r3);
        __nv_bfloat162 l01 = __floats2bfloat162_rn(r0 - __low2float(h01), r1 - __high2float(h01));
        __nv_bfloat162 l23 = __floats2bfloat162_rn(r2 - __low2float(h23), r3 - __high2float(h23));
        uint2 uh = make_uint2(reinterpret_cast<uint32_t&>(h01), reinterpret_cast<uint32_t&>(h23));
        uint2 ul = make_uint2(reinterpret_cast<uint32_t&>(l01), reinterpret_cast<uint32_t&>(l23));
        reinterpret_cast<uint2*>(g_OEh)[i] = uh;
        reinterpret_cast<uint2*>(g_OEl)[i] = ul;
    }
    {
        const float4* d0 = reinterpret_cast<const float4*>(out_d + ((size_t)s * BATCH + b) * HD);
        float4 q = d0[h4];
        __nv_bfloat162 h01 = __floats2bfloat162_rn(q.x, q.y);
        __nv_bfloat162 h23 = __floats2bfloat162_rn(q.z, q.w);
        __nv_bfloat162 l01 = __floats2bfloat162_rn(q.x - __low2float(h01), q.y - __high2float(h01));
        __nv_bfloat162 l23 = __floats2bfloat162_rn(q.z - __low2float(h23), q.w - __high2float(h23));
        uint2 uh = make_uint2(reinterpret_cast<uint32_t&>(h01), reinterpret_cast<uint32_t&>(h23));
        uint2 ul = make_uint2(reinterpret_cast<uint32_t&>(l01), reinterpret_cast<uint32_t&>(l23));
        reinterpret_cast<uint2*>(g_Qh)[i] = uh;
        reinterpret_cast<uint2*>(g_Ql)[i] = ul;
    }
}

// ----------------------------------------------------------------
// transpose hi/lo: OET[b][h][s] = OE[b][s][h]
// ----------------------------------------------------------------
__global__ __launch_bounds__(256) void transpose_kernel()
{
    __shared__ unsigned short th[32][33];
    __shared__ unsigned short tl[32][33];
    const int b  = blockIdx.z;
    const int s0 = blockIdx.x * 32;
    const int h0 = blockIdx.y * 32;
    const unsigned short* sh = reinterpret_cast<const unsigned short*>(g_OEh) + (size_t)b * SRC * HD;
    const unsigned short* sl = reinterpret_cast<const unsigned short*>(g_OEl) + (size_t)b * SRC * HD;
    unsigned short* dh = reinterpret_cast<unsigned short*>(g_OETh) + (size_t)b * HD * SRC;
    unsigned short* dl = reinterpret_cast<unsigned short*>(g_OETl) + (size_t)b * HD * SRC;
    const int x = threadIdx.x;
    const int y = threadIdx.y;

    #pragma unroll
    for (int i = 0; i < 32; i += 8) {
        th[y + i][x] = sh[(size_t)(s0 + y + i) * HD + h0 + x];
        tl[y + i][x] = sl[(size_t)(s0 + y + i) * HD + h0 + x];
    }
    __syncthreads();
    #pragma unroll
    for (int i = 0; i < 32; i += 8) {
        dh[(size_t)(h0 + y + i) * SRC + s0 + x] = th[x][y + i];
        dl[(size_t)(h0 + y + i) * SRC + s0 + x] = tl[x][y + i];
    }
}

// ----------------------------------------------------------------
// QK: att[b][t][s] = Q[b][t][:] . OE[b][s][:]  (fp32 logits)
// CTA tile 128(t) x 256(s)
// ----------------------------------------------------------------
__global__ __launch_bounds__(256, 1) void gemm_qk_mma()
{
    extern __shared__ char smem[];
    const uint32_t s0 = smem_u32(smem);
    const int tid = threadIdx.x;
    const int b = blockIdx.z;
    const int rowBase = blockIdx.y * 128;
    const int colBase = blockIdx.x * 256;

    const bf16* Ah = g_Qh  + ((size_t)b * TGT + rowBase) * HD;
    const bf16* Al = g_Ql  + ((size_t)b * TGT + rowBase) * HD;
    const bf16* Bh = g_OEh + ((size_t)b * SRC + colBase) * HD;
    const bf16* Bl = g_OEl + ((size_t)b * SRC + colBase) * HD;

    float acc[4][8][4];
    #pragma unroll
    for (int i = 0; i < 4; ++i)
        #pragma unroll
        for (int j = 0; j < 8; ++j)
            #pragma unroll
            for (int k = 0; k < 4; ++k) acc[i][j][k] = 0.f;

    mma_mainloop<HD>(Ah, Al, HD, Bh, Bl, HD, acc, s0, tid);

    float* C = g_ATT + (size_t)b * TGT * SRC;
    const int lane = tid & 31, wid = tid >> 5, wm = wid & 1, wn = wid >> 1;
    const int group = lane >> 2, q = lane & 3;
    #pragma unroll
    for (int mi = 0; mi < 4; ++mi) {
        #pragma unroll
        for (int ni = 0; ni < 8; ++ni) {
            const int r0 = rowBase + wm * 64 + mi * 16 + group;
            const int c0 = colBase + wn * 64 + ni * 8 + q * 2;
            *reinterpret_cast<float2*>(C + (size_t)r0 * SRC + c0) =
                make_float2(acc[mi][ni][0], acc[mi][ni][1]);
            *reinterpret_cast<float2*>(C + (size_t)(r0 + 8) * SRC + c0) =
                make_float2(acc[mi][ni][2], acc[mi][ni][3]);
        }
    }
}

// ----------------------------------------------------------------
// softmax over s, writes split-bf16 P
// ----------------------------------------------------------------
__global__ __launch_bounds__(256) void softmax_split_kernel()
{
    const size_t row = blockIdx.x;
    const float* __restrict__ p = g_ATT + row * SRC;
    bf16* __restrict__ ph = g_Ph + row * SRC;
    bf16* __restrict__ pl = g_Pl + row * SRC;
    const int tid = threadIdx.x;

    __shared__ float redm[8];
    __shared__ float reds[8];

    float v[8];
    float m = -INFINITY;
    #pragma unroll
    for (int i = 0; i < 8; ++i) {
        v[i] = p[tid + i * 256];
        m = fmaxf(m, v[i]);
    }
    #pragma unroll
    for (int o = 16; o > 0; o >>= 1) m = fmaxf(m, __shfl_xor_sync(0xffffffffu, m, o));
    if ((tid & 31) == 0) redm[tid >> 5] = m;
    __syncthreads();
    float mAll = redm[0];
    #pragma unroll
    for (int w = 1; w < 8; ++w) mAll = fmaxf(mAll, redm[w]);

    float s = 0.f;
    #pragma unroll
    for (int i = 0; i < 8; ++i) {
        v[i] = __expf(v[i] - mAll);
        s += v[i];
    }
    #pragma unroll
    for (int o = 16; o > 0; o >>= 1) s += __shfl_xor_sync(0xffffffffu, s, o);
    if ((tid & 31) == 0) reds[tid >> 5] = s;
    __syncthreads();
    float sAll = 0.f;
    #pragma unroll
    for (int w = 0; w < 8; ++w) sAll += reds[w];

    const float inv = 1.0f / sAll;
    #pragma unroll
    for (int i = 0; i < 8; ++i) {
        float pv = v[i] * inv;
        bf16 hi = __float2bfloat16_rn(pv);
        bf16 lo = __float2bfloat16_rn(pv - __bfloat162float(hi));
        ph[tid + i * 256] = hi;
        pl[tid + i * 256] = lo;
    }
}

// ----------------------------------------------------------------
// PV: out[t][b][h] = sum_s P[b][t][s] * OET[b][h][s]
// CTA tile 128(t) x 256(h)
// ----------------------------------------------------------------
__global__ __launch_bounds__(256, 1) void gemm_pv_mma(float* __restrict__ out)
{
    extern __shared__ char smem[];
    const uint32_t s0 = smem_u32(smem);
    const int tid = threadIdx.x;
    const int b = blockIdx.z;
    const int rowBase = blockIdx.y * 128;   // t
    const int colBase = blockIdx.x * 256;   // h

    const bf16* Ah = g_Ph   + ((size_t)b * TGT + rowBase) * SRC;
    const bf16* Al = g_Pl   + ((size_t)b * TGT + rowBase) * SRC;
    const bf16* Bh = g_OETh + ((size_t)b * HD + colBase) * SRC;
    const bf16* Bl = g_OETl + ((size_t)b * HD + colBase) * SRC;

    float acc[4][8][4];
    #pragma unroll
    for (int i = 0; i < 4; ++i)
        #pragma unroll
        for (int j = 0; j < 8; ++j)
            #pragma unroll
            for (int k = 0; k < 4; ++k) acc[i][j][k] = 0.f;

    mma_mainloop<SRC>(Ah, Al, SRC, Bh, Bl, SRC, acc, s0, tid);

    const int lane = tid & 31, wid = tid >> 5, wm = wid & 1, wn = wid >> 1;
    const int group = lane >> 2, q = lane & 3;
    #pragma unroll
    for (int mi = 0; mi < 4; ++mi) {
        #pragma unroll
        for (int ni = 0; ni < 8; ++ni) {
            const int t0 = rowBase + wm * 64 + mi * 16 + group;
            const int c0 = colBase + wn * 64 + ni * 8 + q * 2;
            *reinterpret_cast<float2*>(out + ((size_t)t0 * BATCH + b) * HD + c0) =
                make_float2(acc[mi][ni][0], acc[mi][ni][1]);
            *reinterpret_cast<float2*>(out + ((size_t)(t0 + 8) * BATCH + b) * HD + c0) =
                make_float2(acc[mi][ni][2], acc[mi][ni][3]);
        }
    }
}

// ----------------------------------------------------------------
extern "C" void kernel_launch(void* const* d_in, const int* in_sizes, int n_in,
                              void* d_out, int out_size)
{
    (void)in_sizes; (void)n_in; (void)out_size;
    const float* out_e = (const float*)d_in[1];   // [SRC][B][2H]
    const float* out_d = (const float*)d_in[2];   // [TGT][B][H]
    float* out = (float*)d_out;                   // [TGT][B][H]

    cudaFuncSetAttribute(gemm_qk_mma, cudaFuncAttributeMaxDynamicSharedMemorySize, SMEM_GEMM);
    cudaFuncSetAttribute(gemm_pv_mma, cudaFuncAttributeMaxDynamicSharedMemorySize, SMEM_GEMM);

    const int prepTotal = BATCH * SRC * (HD / 4);
    prep_kernel<<<prepTotal / 256, 256>>>(out_e, out_d);

    dim3 gt(SRC / 32, HD / 32, BATCH);
    transpose_kernel<<<gt, dim3(32, 8)>>>();

    dim3 g1(SRC / 256, TGT / 128, BATCH);                  // 8 x 16 x 16
    gemm_qk_mma<<<g1, 256, SMEM_GEMM>>>();

    softmax_split_kernel<<<BATCH * TGT, 256>>>();

    dim3 g2(HD / 256, TGT / 128, BATCH);                   // 2 x 16 x 16
    gemm_pv_mma<<<g2, 256, SMEM_GEMM>>>(out);
}

// round 9
// speedup vs baseline: 2.4809x; 1.0777x over previous
#include <cuda_runtime.h>
#include <cuda_bf16.h>
#include <math.h>
#include <stdint.h>

#define SRC   2048
#define TGT   2048
#define BATCH 16
#define HD    512

typedef __nv_bfloat16 bf16;

// -------- scratch (device globals; no runtime allocation) --------
__device__ bf16  g_Qh [(size_t)BATCH * TGT * HD];
__device__ bf16  g_Ql [(size_t)BATCH * TGT * HD];
__device__ bf16  g_OEh[(size_t)BATCH * SRC * HD];
__device__ bf16  g_OEl[(size_t)BATCH * SRC * HD];
__device__ bf16  g_OETh[(size_t)BATCH * HD * SRC];
__device__ bf16  g_OETl[(size_t)BATCH * HD * SRC];
__device__ float g_ATT[(size_t)BATCH * TGT * SRC];   // fp32 logits
__device__ bf16  g_Ph [(size_t)BATCH * TGT * SRC];
__device__ bf16  g_Pl [(size_t)BATCH * TGT * SRC];

// ================= helpers =================
__device__ __forceinline__ uint32_t smem_u32(const void* p) {
    uint32_t a;
    asm("{ .reg .u64 t; cvta.to.shared.u64 t, %1; cvt.u32.u64 %0, t; }"
        : "=r"(a) : "l"(p));
    return a;
}

#define LDSM4(r, addr)                                                        \
    asm volatile("ldmatrix.sync.aligned.m8n8.x4.shared.b16 {%0,%1,%2,%3}, [%4];" \
                 : "=r"((r)[0]), "=r"((r)[1]), "=r"((r)[2]), "=r"((r)[3])     \
                 : "r"(addr))

#define MMA16816(c, a, b0, b1)                                                \
    asm volatile("mma.sync.aligned.m16n8k16.row.col.f32.bf16.bf16.f32 "       \
                 "{%0,%1,%2,%3},{%4,%5,%6,%7},{%8,%9},{%0,%1,%2,%3};"         \
                 : "+f"((c)[0]), "+f"((c)[1]), "+f"((c)[2]), "+f"((c)[3])     \
                 : "r"((a)[0]), "r"((a)[1]), "r"((a)[2]), "r"((a)[3]),        \
                   "r"(b0), "r"(b1))

#define CP16(dst, src)                                                        \
    asm volatile("cp.async.cg.shared.global [%0], [%1], 16;" :: "r"(dst), "l"(src))
#define CP_COMMIT() asm volatile("cp.async.commit_group;" ::: "memory")
#define CP_WAIT1()  asm volatile("cp.async.wait_group 1;" ::: "memory")

// K-chunk 64. Row stride 72 bf16 (144 B) — ldmatrix conflict-free (36i mod 32 distinct).
// Tile = 128 rows x 72 cols x 2B = 18432 B.
// Stage: Ah | Al | Bh | Bl = 4 x 18432 = 73728 B; 3 stages = 221184 B (< 227 KB).
#define TILE_B   18432
#define OFF_AL   18432
#define OFF_BH   36864
#define OFF_BL   55296
#define STAGE_B  73728
#define NSTAGE   3
#define SMEM_GEMM (STAGE_B * NSTAGE)   // 221184
#define KCHUNK   64

// async-copy 128x64 bf16 (row stride ld) -> smem stride 72 ; 4 CP16/thread
__device__ __forceinline__ void cpT(const bf16* __restrict__ g, size_t ld, int k0,
                                    uint32_t sbase, int tid) {
    #pragma unroll
    for (int i = 0; i < 4; ++i) {
        int v = i * 256 + tid;           // 0..1023
        int row = v >> 3;
        int c = v & 7;
        CP16(sbase + (uint32_t)(row * 72 + c * 8) * 2u, g + (size_t)row * ld + k0 + c * 8);
    }
}

// Mainloop: acc(64x32 per warp) += A(128xK) * B(128xK)^T, split-bf16 3-MMA.
// 3-stage cp.async pipeline, K-chunk 64, single __syncthreads per chunk.
template <int KTOT>
__device__ __forceinline__ void mma_mainloop(const bf16* __restrict__ Ah, const bf16* __restrict__ Al,
                                             size_t lda,
                                             const bf16* __restrict__ Bh, const bf16* __restrict__ Bl,
                                             size_t ldb,
                                             float (&acc)[4][4][4], uint32_t s0, int tid)
{
    const int NC = KTOT / KCHUNK;
    const int lane = tid & 31;
    const int wid = tid >> 5;
    const int wm = wid & 1;       // 2 warps over M (64 rows each)
    const int wn = wid >> 1;      // 4 warps over N (32 cols each)

    const int aRow = wm * 64 + (lane & 15);
    const int aCol = (lane >> 4) << 3;
    const int bRow = wn * 32 + (lane & 7) + ((lane >> 4) << 3);
    const int bCol = lane & 8;

    // prologue: prefetch chunks 0,1
    #pragma unroll
    for (int p = 0; p < 2; ++p) {
        uint32_t sb = s0 + p * STAGE_B;
        cpT(Ah, lda, p * KCHUNK, sb,          tid);
        cpT(Al, lda, p * KCHUNK, sb + OFF_AL, tid);
        cpT(Bh, ldb, p * KCHUNK, sb + OFF_BH, tid);
        cpT(Bl, ldb, p * KCHUNK, sb + OFF_BL, tid);
        CP_COMMIT();
    }

    for (int kc = 0; kc < NC; ++kc) {
        CP_WAIT1();                      // chunk kc resident
        __syncthreads();                 // all warps done with the stage we overwrite

        // prefetch chunk kc+2 (empty commit on tail keeps group ledger aligned)
        if (kc + 2 < NC) {
            uint32_t sb = s0 + ((kc + 2) % NSTAGE) * STAGE_B;
            const int k0 = (kc + 2) * KCHUNK;
            cpT(Ah, lda, k0, sb,          tid);
            cpT(Al, lda, k0, sb + OFF_AL, tid);
            cpT(Bh, ldb, k0, sb + OFF_BH, tid);
            cpT(Bl, ldb, k0, sb + OFF_BL, tid);
        }
        CP_COMMIT();

        const uint32_t st = s0 + (kc % NSTAGE) * STAGE_B;
        const uint32_t As_h = st, As_l = st + OFF_AL;
        const uint32_t Bs_h = st + OFF_BH, Bs_l = st + OFF_BL;

        #pragma unroll
        for (int k16 = 0; k16 < 4; ++k16) {
            const int kOff = k16 * 16;
            uint32_t a_h[4][4], a_l[4][4];

            #pragma unroll
            for (int mi = 0; mi < 4; ++mi) {
                uint32_t off = (uint32_t)((aRow + mi * 16) * 72 + kOff + aCol) * 2u;
                LDSM4(a_h[mi], As_h + off);
                LDSM4(a_l[mi], As_l + off);
            }
            #pragma unroll
            for (int n2 = 0; n2 < 2; ++n2) {
                uint32_t b_h[4], b_l[4];
                uint32_t off = (uint32_t)((bRow + n2 * 16) * 72 + kOff + bCol) * 2u;
                LDSM4(b_h, Bs_h + off);
                LDSM4(b_l, Bs_l + off);

                #pragma unroll
                for (int half = 0; half < 2; ++half) {
                    const int ni = n2 * 2 + half;
                    const int sb = half * 2;
                    #pragma unroll
                    for (int mi = 0; mi < 4; ++mi) {
                        MMA16816(acc[mi][ni], a_h[mi], b_h[sb], b_h[sb + 1]); // hi*hi
                        MMA16816(acc[mi][ni], a_h[mi], b_l[sb], b_l[sb + 1]); // hi*lo
                        MMA16816(acc[mi][ni], a_l[mi], b_h[sb], b_h[sb + 1]); // lo*hi
                    }
                }
            }
        }
    }
    __syncthreads();
}

// ----------------------------------------------------------------
// prep: oe = fwd+bwd half sum -> hi/lo bf16 [B][S][H];  q -> hi/lo bf16 [B][T][H]
// ----------------------------------------------------------------
__global__ __launch_bounds__(256) void prep_kernel(const float* __restrict__ out_e,
                                                   const float* __restrict__ out_d)
{
    const size_t i = (size_t)blockIdx.x * blockDim.x + threadIdx.x;   // B*S*(H/4)
    const size_t total = (size_t)BATCH * SRC * (HD / 4);
    if (i >= total) return;

    const int h4 = (int)(i % (HD / 4));
    const size_t bs = i / (HD / 4);
    const int s = (int)(bs % SRC);
    const int b = (int)(bs / SRC);

    {
        const float4* e0 = reinterpret_cast<const float4*>(out_e + ((size_t)s * BATCH + b) * (2 * HD));
        float4 x = e0[h4];
        float4 y = e0[HD / 4 + h4];
        float r0 = x.x + y.x, r1 = x.y + y.y, r2 = x.z + y.z, r3 = x.w + y.w;

        __nv_bfloat162 h01 = __floats2bfloat162_rn(r0, r1);
        __nv_bfloat162 h23 = __floats2bfloat162_rn(r2, r3);
        __nv_bfloat162 l01 = __floats2bfloat162_rn(r0 - __low2float(h01), r1 - __high2float(h01));
        __nv_bfloat162 l23 = __floats2bfloat162_rn(r2 - __low2float(h23), r3 - __high2float(h23));
        uint2 uh = make_uint2(reinterpret_cast<uint32_t&>(h01), reinterpret_cast<uint32_t&>(h23));
        uint2 ul = make_uint2(reinterpret_cast<uint32_t&>(l01), reinterpret_cast<uint32_t&>(l23));
        reinterpret_cast<uint2*>(g_OEh)[i] = uh;
        reinterpret_cast<uint2*>(g_OEl)[i] = ul;
    }
    {
        const float4* d0 = reinterpret_cast<const float4*>(out_d + ((size_t)s * BATCH + b) * HD);
        float4 q = d0[h4];
        __nv_bfloat162 h01 = __floats2bfloat162_rn(q.x, q.y);
        __nv_bfloat162 h23 = __floats2bfloat162_rn(q.z, q.w);
        __nv_bfloat162 l01 = __floats2bfloat162_rn(q.x - __low2float(h01), q.y - __high2float(h01));
        __nv_bfloat162 l23 = __floats2bfloat162_rn(q.z - __low2float(h23), q.w - __high2float(h23));
        uint2 uh = make_uint2(reinterpret_cast<uint32_t&>(h01), reinterpret_cast<uint32_t&>(h23));
        uint2 ul = make_uint2(reinterpret_cast<uint32_t&>(l01), reinterpret_cast<uint32_t&>(l23));
        reinterpret_cast<uint2*>(g_Qh)[i] = uh;
        reinterpret_cast<uint2*>(g_Ql)[i] = ul;
    }
}

// ----------------------------------------------------------------
// transpose hi/lo: OET[b][h][s] = OE[b][s][h]
// ----------------------------------------------------------------
__global__ __launch_bounds__(256) void transpose_kernel()
{
    __shared__ unsigned short th[32][33];
    __shared__ unsigned short tl[32][33];
    const int b  = blockIdx.z;
    const int s0 = blockIdx.x * 32;
    const int h0 = blockIdx.y * 32;
    const unsigned short* sh = reinterpret_cast<const unsigned short*>(g_OEh) + (size_t)b * SRC * HD;
    const unsigned short* sl = reinterpret_cast<const unsigned short*>(g_OEl) + (size_t)b * SRC * HD;
    unsigned short* dh = reinterpret_cast<unsigned short*>(g_OETh) + (size_t)b * HD * SRC;
    unsigned short* dl = reinterpret_cast<unsigned short*>(g_OETl) + (size_t)b * HD * SRC;
    const int x = threadIdx.x;
    const int y = threadIdx.y;

    #pragma unroll
    for (int i = 0; i < 32; i += 8) {
        th[y + i][x] = sh[(size_t)(s0 + y + i) * HD + h0 + x];
        tl[y + i][x] = sl[(size_t)(s0 + y + i) * HD + h0 + x];
    }
    __syncthreads();
    #pragma unroll
    for (int i = 0; i < 32; i += 8) {
        dh[(size_t)(h0 + y + i) * SRC + s0 + x] = th[x][y + i];
        dl[(size_t)(h0 + y + i) * SRC + s0 + x] = tl[x][y + i];
    }
}

// ----------------------------------------------------------------
// QK: att[b][t][s] = Q[b][t][:] . OE[b][s][:]  (fp32 logits)
// CTA tile 128(t) x 128(s), K-chunk 64
// ----------------------------------------------------------------
__global__ __launch_bounds__(256, 1) void gemm_qk_mma()
{
    extern __shared__ char smem[];
    const uint32_t s0 = smem_u32(smem);
    const int tid = threadIdx.x;
    const int b = blockIdx.z;
    const int rowBase = blockIdx.y * 128;
    const int colBase = blockIdx.x * 128;

    const bf16* Ah = g_Qh  + ((size_t)b * TGT + rowBase) * HD;
    const bf16* Al = g_Ql  + ((size_t)b * TGT + rowBase) * HD;
    const bf16* Bh = g_OEh + ((size_t)b * SRC + colBase) * HD;
    const bf16* Bl = g_OEl + ((size_t)b * SRC + colBase) * HD;

    float acc[4][4][4];
    #pragma unroll
    for (int i = 0; i < 4; ++i)
        #pragma unroll
        for (int j = 0; j < 4; ++j)
            #pragma unroll
            for (int k = 0; k < 4; ++k) acc[i][j][k] = 0.f;

    mma_mainloop<HD>(Ah, Al, HD, Bh, Bl, HD, acc, s0, tid);

    float* C = g_ATT + (size_t)b * TGT * SRC;
    const int lane = tid & 31, wid = tid >> 5, wm = wid & 1, wn = wid >> 1;
    const int group = lane >> 2, q = lane & 3;
    #pragma unroll
    for (int mi = 0; mi < 4; ++mi) {
        #pragma unroll
        for (int ni = 0; ni < 4; ++ni) {
            const int r0 = rowBase + wm * 64 + mi * 16 + group;
            const int c0 = colBase + wn * 32 + ni * 8 + q * 2;
            *reinterpret_cast<float2*>(C + (size_t)r0 * SRC + c0) =
                make_float2(acc[mi][ni][0], acc[mi][ni][1]);
            *reinterpret_cast<float2*>(C + (size_t)(r0 + 8) * SRC + c0) =
                make_float2(acc[mi][ni][2], acc[mi][ni][3]);
        }
    }
}

// ----------------------------------------------------------------
// softmax over s, writes split-bf16 P
// ----------------------------------------------------------------
__global__ __launch_bounds__(256) void softmax_split_kernel()
{
    const size_t row = blockIdx.x;
    const float* __restrict__ p = g_ATT + row * SRC;
    bf16* __restrict__ ph = g_Ph + row * SRC;
    bf16* __restrict__ pl = g_Pl + row * SRC;
    const int tid = threadIdx.x;

    __shared__ float redm[8];
    __shared__ float reds[8];

    float v[8];
    float m = -INFINITY;
    #pragma unroll
    for (int i = 0; i < 8; ++i) {
        v[i] = p[tid + i * 256];
        m = fmaxf(m, v[i]);
    }
    #pragma unroll
    for (int o = 16; o > 0; o >>= 1) m = fmaxf(m, __shfl_xor_sync(0xffffffffu, m, o));
    if ((tid & 31) == 0) redm[tid >> 5] = m;
    __syncthreads();
    float mAll = redm[0];
    #pragma unroll
    for (int w = 1; w < 8; ++w) mAll = fmaxf(mAll, redm[w]);

    float s = 0.f;
    #pragma unroll
    for (int i = 0; i < 8; ++i) {
        v[i] = __expf(v[i] - mAll);
        s += v[i];
    }
    #pragma unroll
    for (int o = 16; o > 0; o >>= 1) s += __shfl_xor_sync(0xffffffffu, s, o);
    if ((tid & 31) == 0) reds[tid >> 5] = s;
    __syncthreads();
    float sAll = 0.f;
    #pragma unroll
    for (int w = 0; w < 8; ++w) sAll += reds[w];

    const float inv = 1.0f / sAll;
    #pragma unroll
    for (int i = 0; i < 8; ++i) {
        float pv = v[i] * inv;
        bf16 hi = __float2bfloat16_rn(pv);
        bf16 lo = __float2bfloat16_rn(pv - __bfloat162float(hi));
        ph[tid + i * 256] = hi;
        pl[tid + i * 256] = lo;
    }
}

// ----------------------------------------------------------------
// PV: out[t][b][h] = sum_s P[b][t][s] * OET[b][h][s]
// CTA tile 128(t) x 128(h), K-chunk 64
// ----------------------------------------------------------------
__global__ __launch_bounds__(256, 1) void gemm_pv_mma(float* __restrict__ out)
{
    extern __shared__ char smem[];
    const uint32_t s0 = smem_u32(smem);
    const int tid = threadIdx.x;
    const int b = blockIdx.z;
    const int rowBase = blockIdx.y * 128;   // t
    const int colBase = blockIdx.x * 128;   // h

    const bf16* Ah = g_Ph   + ((size_t)b * TGT + rowBase) * SRC;
    const bf16* Al = g_Pl   + ((size_t)b * TGT + rowBase) * SRC;
    const bf16* Bh = g_OETh + ((size_t)b * HD + colBase) * SRC;
    const bf16* Bl = g_OETl + ((size_t)b * HD + colBase) * SRC;

    float acc[4][4][4];
    #pragma unroll
    for (int i = 0; i < 4; ++i)
        #pragma unroll
        for (int j = 0; j < 4; ++j)
            #pragma unroll
            for (int k = 0; k < 4; ++k) acc[i][j][k] = 0.f;

    mma_mainloop<SRC>(Ah, Al, SRC, Bh, Bl, SRC, acc, s0, tid);

    const int lane = tid & 31, wid = tid >> 5, wm = wid & 1, wn = wid >> 1;
    const int group = lane >> 2, q = lane & 3;
    #pragma unroll
    for (int mi = 0; mi < 4; ++mi) {
        #pragma unroll
        for (int ni = 0; ni < 4; ++ni) {
            const int t0 = rowBase + wm * 64 + mi * 16 + group;
            const int c0 = colBase + wn * 32 + ni * 8 + q * 2;
            *reinterpret_cast<float2*>(out + ((size_t)t0 * BATCH + b) * HD + c0) =
                make_float2(acc[mi][ni][0], acc[mi][ni][1]);
            *reinterpret_cast<float2*>(out + ((size_t)(t0 + 8) * BATCH + b) * HD + c0) =
                make_float2(acc[mi][ni][2], acc[mi][ni][3]);
        }
    }
}

// ----------------------------------------------------------------
extern "C" void kernel_launch(void* const* d_in, const int* in_sizes, int n_in,
                              void* d_out, int out_size)
{
    (void)in_sizes; (void)n_in; (void)out_size;
    const float* out_e = (const float*)d_in[1];   // [SRC][B][2H]
    const float* out_d = (const float*)d_in[2];   // [TGT][B][H]
    float* out = (float*)d_out;                   // [TGT][B][H]

    cudaFuncSetAttribute(gemm_qk_mma, cudaFuncAttributeMaxDynamicSharedMemorySize, SMEM_GEMM);
    cudaFuncSetAttribute(gemm_pv_mma, cudaFuncAttributeMaxDynamicSharedMemorySize, SMEM_GEMM);

    const int prepTotal = BATCH * SRC * (HD / 4);
    prep_kernel<<<prepTotal / 256, 256>>>(out_e, out_d);

    dim3 gt(SRC / 32, HD / 32, BATCH);
    transpose_kernel<<<gt, dim3(32, 8)>>>();

    dim3 g1(SRC / 128, TGT / 128, BATCH);                  // 16 x 16 x 16
    gemm_qk_mma<<<g1, 256, SMEM_GEMM>>>();

    softmax_split_kernel<<<BATCH * TGT, 256>>>();

    dim3 g2(HD / 128, TGT / 128, BATCH);                   // 4 x 16 x 16
    gemm_pv_mma<<<g2, 256, SMEM_GEMM>>>(out);
}

// round 10
// speedup vs baseline: 2.8403x; 1.1449x over previous
#include <cuda_runtime.h>
#include <cuda_fp16.h>
#include <math.h>
#include <stdint.h>

#define SRC   2048
#define TGT   2048
#define BATCH 16
#define HD    512

typedef __half fp16;

// -------- scratch (device globals; no runtime allocation) --------
__device__ fp16  g_Qh [(size_t)BATCH * TGT * HD];
__device__ fp16  g_Ql [(size_t)BATCH * TGT * HD];
__device__ fp16  g_OEh[(size_t)BATCH * SRC * HD];
__device__ fp16  g_OEl[(size_t)BATCH * SRC * HD];
__device__ fp16  g_OETh[(size_t)BATCH * HD * SRC];
__device__ fp16  g_OETl[(size_t)BATCH * HD * SRC];
__device__ float g_ATT[(size_t)BATCH * TGT * SRC];   // fp32 logits
__device__ fp16  g_Ph [(size_t)BATCH * TGT * SRC];   // softmax hi only

// ================= helpers =================
__device__ __forceinline__ uint32_t smem_u32(const void* p) {
    uint32_t a;
    asm("{ .reg .u64 t; cvta.to.shared.u64 t, %1; cvt.u32.u64 %0, t; }"
        : "=r"(a) : "l"(p));
    return a;
}

#define LDSM4(r, addr)                                                        \
    asm volatile("ldmatrix.sync.aligned.m8n8.x4.shared.b16 {%0,%1,%2,%3}, [%4];" \
                 : "=r"((r)[0]), "=r"((r)[1]), "=r"((r)[2]), "=r"((r)[3])     \
                 : "r"(addr))

#define MMA16816(c, a, b0, b1)                                                \
    asm volatile("mma.sync.aligned.m16n8k16.row.col.f32.f16.f16.f32 "         \
                 "{%0,%1,%2,%3},{%4,%5,%6,%7},{%8,%9},{%0,%1,%2,%3};"         \
                 : "+f"((c)[0]), "+f"((c)[1]), "+f"((c)[2]), "+f"((c)[3])     \
                 : "r"((a)[0]), "r"((a)[1]), "r"((a)[2]), "r"((a)[3]),        \
                   "r"(b0), "r"(b1))

#define CP16(dst, src)                                                        \
    asm volatile("cp.async.cg.shared.global [%0], [%1], 16;" :: "r"(dst), "l"(src))
#define CP_COMMIT() asm volatile("cp.async.commit_group;" ::: "memory")
#define CP_WAIT1()  asm volatile("cp.async.wait_group 1;" ::: "memory")

// K-chunk 64. Row stride 72 halves (144 B) — ldmatrix conflict-free.
// Tile = 128 rows x 72 cols x 2B = 18432 B.
#define TILE_B   18432u
#define NSTAGE   3
#define KCHUNK   64
#define SMEM_QK  (4 * TILE_B * NSTAGE)   // Ah|Al|Bh|Bl  = 221184
#define SMEM_PV  (3 * TILE_B * NSTAGE)   // Ah|Bh|Bl     = 165888

// async-copy 128x64 fp16 (row stride ld) -> smem stride 72 ; 4 CP16/thread
__device__ __forceinline__ void cpT(const fp16* __restrict__ g, size_t ld, int k0,
                                    uint32_t sbase, int tid) {
    #pragma unroll
    for (int i = 0; i < 4; ++i) {
        int v = i * 256 + tid;           // 0..1023
        int row = v >> 3;
        int c = v & 7;
        CP16(sbase + (uint32_t)(row * 72 + c * 8) * 2u, g + (size_t)row * ld + k0 + c * 8);
    }
}

// Mainloop: acc(64x32 per warp) += A(128xK) * B(128xK)^T.
// ASPLIT=true : 3 MMAs (AhBh + AhBl + AlBh)   [QK]
// ASPLIT=false: 2 MMAs (AhBh + AhBl), no Al   [PV]
template <int KTOT, bool ASPLIT>
__device__ __forceinline__ void mma_mainloop(const fp16* __restrict__ Ah, const fp16* __restrict__ Al,
                                             size_t lda,
                                             const fp16* __restrict__ Bh, const fp16* __restrict__ Bl,
                                             size_t ldb,
                                             float (&acc)[4][4][4], uint32_t s0, int tid)
{
    constexpr uint32_t OFF_AL = TILE_B;
    constexpr uint32_t OFF_BH = ASPLIT ? 2 * TILE_B : TILE_B;
    constexpr uint32_t OFF_BL = OFF_BH + TILE_B;
    constexpr uint32_t STAGE_B = OFF_BL + TILE_B;

    const int NC = KTOT / KCHUNK;
    const int lane = tid & 31;
    const int wid = tid >> 5;
    const int wm = wid & 1;       // 2 warps over M (64 rows each)
    const int wn = wid >> 1;      // 4 warps over N (32 cols each)

    const int aRow = wm * 64 + (lane & 15);
    const int aCol = (lane >> 4) << 3;
    const int bRow = wn * 32 + (lane & 7) + ((lane >> 4) << 3);
    const int bCol = lane & 8;

    // prologue: prefetch chunks 0,1
    #pragma unroll
    for (int p = 0; p < 2; ++p) {
        uint32_t sb = s0 + p * STAGE_B;
        cpT(Ah, lda, p * KCHUNK, sb,          tid);
        if (ASPLIT) cpT(Al, lda, p * KCHUNK, sb + OFF_AL, tid);
        cpT(Bh, ldb, p * KCHUNK, sb + OFF_BH, tid);
        cpT(Bl, ldb, p * KCHUNK, sb + OFF_BL, tid);
        CP_COMMIT();
    }

    for (int kc = 0; kc < NC; ++kc) {
        CP_WAIT1();                      // chunk kc resident
        __syncthreads();                 // all warps done with the stage we overwrite

        // prefetch chunk kc+2 (empty commit on tail keeps group ledger aligned)
        if (kc + 2 < NC) {
            uint32_t sb = s0 + ((kc + 2) % NSTAGE) * STAGE_B;
            const int k0 = (kc + 2) * KCHUNK;
            cpT(Ah, lda, k0, sb,          tid);
            if (ASPLIT) cpT(Al, lda, k0, sb + OFF_AL, tid);
            cpT(Bh, ldb, k0, sb + OFF_BH, tid);
            cpT(Bl, ldb, k0, sb + OFF_BL, tid);
        }
        CP_COMMIT();

        const uint32_t st = s0 + (kc % NSTAGE) * STAGE_B;
        const uint32_t As_h = st, As_l = st + OFF_AL;
        const uint32_t Bs_h = st + OFF_BH, Bs_l = st + OFF_BL;

        #pragma unroll
        for (int k16 = 0; k16 < 4; ++k16) {
            const int kOff = k16 * 16;
            uint32_t a_h[4][4], a_l[4][4];

            #pragma unroll
            for (int mi = 0; mi < 4; ++mi) {
                uint32_t off = (uint32_t)((aRow + mi * 16) * 72 + kOff + aCol) * 2u;
                LDSM4(a_h[mi], As_h + off);
                if (ASPLIT) LDSM4(a_l[mi], As_l + off);
            }
            #pragma unroll
            for (int n2 = 0; n2 < 2; ++n2) {
                uint32_t b_h[4], b_l[4];
                uint32_t off = (uint32_t)((bRow + n2 * 16) * 72 + kOff + bCol) * 2u;
                LDSM4(b_h, Bs_h + off);
                LDSM4(b_l, Bs_l + off);

                #pragma unroll
                for (int half = 0; half < 2; ++half) {
                    const int ni = n2 * 2 + half;
                    const int sb = half * 2;
                    #pragma unroll
                    for (int mi = 0; mi < 4; ++mi) {
                        MMA16816(acc[mi][ni], a_h[mi], b_h[sb], b_h[sb + 1]);              // hi*hi
                        MMA16816(acc[mi][ni], a_h[mi], b_l[sb], b_l[sb + 1]);              // hi*lo
                        if (ASPLIT) MMA16816(acc[mi][ni], a_l[mi], b_h[sb], b_h[sb + 1]);  // lo*hi
                    }
                }
            }
        }
    }
    __syncthreads();
}

// ----------------------------------------------------------------
// prep: oe = fwd+bwd half sum -> hi/lo fp16 [B][S][H];  q -> hi/lo fp16 [B][T][H]
// ----------------------------------------------------------------
__device__ __forceinline__ void split4(float r0, float r1, float r2, float r3,
                                       uint2& uh, uint2& ul) {
    __half2 h01 = __floats2half2_rn(r0, r1);
    __half2 h23 = __floats2half2_rn(r2, r3);
    __half2 l01 = __floats2half2_rn(r0 - __low2float(h01), r1 - __high2float(h01));
    __half2 l23 = __floats2half2_rn(r2 - __low2float(h23), r3 - __high2float(h23));
    uh = make_uint2(reinterpret_cast<uint32_t&>(h01), reinterpret_cast<uint32_t&>(h23));
    ul = make_uint2(reinterpret_cast<uint32_t&>(l01), reinterpret_cast<uint32_t&>(l23));
}

__global__ __launch_bounds__(256) void prep_kernel(const float* __restrict__ out_e,
                                                   const float* __restrict__ out_d)
{
    const size_t i = (size_t)blockIdx.x * blockDim.x + threadIdx.x;   // B*S*(H/4)
    const size_t total = (size_t)BATCH * SRC * (HD / 4);
    if (i >= total) return;

    const int h4 = (int)(i % (HD / 4));
    const size_t bs = i / (HD / 4);
    const int s = (int)(bs % SRC);
    const int b = (int)(bs / SRC);

    {
        const float4* e0 = reinterpret_cast<const float4*>(out_e + ((size_t)s * BATCH + b) * (2 * HD));
        float4 x = e0[h4];
        float4 y = e0[HD / 4 + h4];
        uint2 uh, ul;
        split4(x.x + y.x, x.y + y.y, x.z + y.z, x.w + y.w, uh, ul);
        reinterpret_cast<uint2*>(g_OEh)[i] = uh;
        reinterpret_cast<uint2*>(g_OEl)[i] = ul;
    }
    {
        const float4* d0 = reinterpret_cast<const float4*>(out_d + ((size_t)s * BATCH + b) * HD);
        float4 q = d0[h4];
        uint2 uh, ul;
        split4(q.x, q.y, q.z, q.w, uh, ul);
        reinterpret_cast<uint2*>(g_Qh)[i] = uh;
        reinterpret_cast<uint2*>(g_Ql)[i] = ul;
    }
}

// ----------------------------------------------------------------
// transpose hi/lo: OET[b][h][s] = OE[b][s][h]  (per-element split is layout-free)
// ----------------------------------------------------------------
__global__ __launch_bounds__(256) void transpose_kernel()
{
    __shared__ unsigned short th[32][33];
    __shared__ unsigned short tl[32][33];
    const int b  = blockIdx.z;
    const int s0 = blockIdx.x * 32;
    const int h0 = blockIdx.y * 32;
    const unsigned short* sh = reinterpret_cast<const unsigned short*>(g_OEh) + (size_t)b * SRC * HD;
    const unsigned short* sl = reinterpret_cast<const unsigned short*>(g_OEl) + (size_t)b * SRC * HD;
    unsigned short* dh = reinterpret_cast<unsigned short*>(g_OETh) + (size_t)b * HD * SRC;
    unsigned short* dl = reinterpret_cast<unsigned short*>(g_OETl) + (size_t)b * HD * SRC;
    const int x = threadIdx.x;
    const int y = threadIdx.y;

    #pragma unroll
    for (int i = 0; i < 32; i += 8) {
        th[y + i][x] = sh[(size_t)(s0 + y + i) * HD + h0 + x];
        tl[y + i][x] = sl[(size_t)(s0 + y + i) * HD + h0 + x];
    }
    __syncthreads();
    #pragma unroll
    for (int i = 0; i < 32; i += 8) {
        dh[(size_t)(h0 + y + i) * SRC + s0 + x] = th[x][y + i];
        dl[(size_t)(h0 + y + i) * SRC + s0 + x] = tl[x][y + i];
    }
}

// ----------------------------------------------------------------
// QK: att[b][t][s] = Q[b][t][:] . OE[b][s][:]  (fp32 logits)
// CTA tile 128(t) x 128(s), K-chunk 64, fp16 3-term
// ----------------------------------------------------------------
__global__ __launch_bounds__(256, 1) void gemm_qk_mma()
{
    extern __shared__ char smem[];
    const uint32_t s0 = smem_u32(smem);
    const int tid = threadIdx.x;
    const int b = blockIdx.z;
    const int rowBase = blockIdx.y * 128;
    const int colBase = blockIdx.x * 128;

    const fp16* Ah = g_Qh  + ((size_t)b * TGT + rowBase) * HD;
    const fp16* Al = g_Ql  + ((size_t)b * TGT + rowBase) * HD;
    const fp16* Bh = g_OEh + ((size_t)b * SRC + colBase) * HD;
    const fp16* Bl = g_OEl + ((size_t)b * SRC + colBase) * HD;

    float acc[4][4][4];
    #pragma unroll
    for (int i = 0; i < 4; ++i)
        #pragma unroll
        for (int j = 0; j < 4; ++j)
            #pragma unroll
            for (int k = 0; k < 4; ++k) acc[i][j][k] = 0.f;

    mma_mainloop<HD, true>(Ah, Al, HD, Bh, Bl, HD, acc, s0, tid);

    float* C = g_ATT + (size_t)b * TGT * SRC;
    const int lane = tid & 31, wid = tid >> 5, wm = wid & 1, wn = wid >> 1;
    const int group = lane >> 2, q = lane & 3;
    #pragma unroll
    for (int mi = 0; mi < 4; ++mi) {
        #pragma unroll
        for (int ni = 0; ni < 4; ++ni) {
            const int r0 = rowBase + wm * 64 + mi * 16 + group;
            const int c0 = colBase + wn * 32 + ni * 8 + q * 2;
            *reinterpret_cast<float2*>(C + (size_t)r0 * SRC + c0) =
                make_float2(acc[mi][ni][0], acc[mi][ni][1]);
            *reinterpret_cast<float2*>(C + (size_t)(r0 + 8) * SRC + c0) =
                make_float2(acc[mi][ni][2], acc[mi][ni][3]);
        }
    }
}

// ----------------------------------------------------------------
// softmax over s, writes fp16 P (hi only)
// ----------------------------------------------------------------
__global__ __launch_bounds__(256) void softmax_split_kernel()
{
    const size_t row = blockIdx.x;
    const float* __restrict__ p = g_ATT + row * SRC;
    fp16* __restrict__ ph = g_Ph + row * SRC;
    const int tid = threadIdx.x;

    __shared__ float redm[8];
    __shared__ float reds[8];

    float v[8];
    float m = -INFINITY;
    #pragma unroll
    for (int i = 0; i < 8; ++i) {
        v[i] = p[tid + i * 256];
        m = fmaxf(m, v[i]);
    }
    #pragma unroll
    for (int o = 16; o > 0; o >>= 1) m = fmaxf(m, __shfl_xor_sync(0xffffffffu, m, o));
    if ((tid & 31) == 0) redm[tid >> 5] = m;
    __syncthreads();
    float mAll = redm[0];
    #pragma unroll
    for (int w = 1; w < 8; ++w) mAll = fmaxf(mAll, redm[w]);

    float s = 0.f;
    #pragma unroll
    for (int i = 0; i < 8; ++i) {
        v[i] = __expf(v[i] - mAll);
        s += v[i];
    }
    #pragma unroll
    for (int o = 16; o > 0; o >>= 1) s += __shfl_xor_sync(0xffffffffu, s, o);
    if ((tid & 31) == 0) reds[tid >> 5] = s;
    __syncthreads();
    float sAll = 0.f;
    #pragma unroll
    for (int w = 0; w < 8; ++w) sAll += reds[w];

    const float inv = 1.0f / sAll;
    #pragma unroll
    for (int i = 0; i < 8; ++i)
        ph[tid + i * 256] = __float2half_rn(v[i] * inv);
}

// ----------------------------------------------------------------
// PV: out[t][b][h] = sum_s P[b][t][s] * OET[b][h][s]
// CTA tile 128(t) x 128(h), K-chunk 64, fp16 2-term (P hi only)
// ----------------------------------------------------------------
__global__ __launch_bounds__(256, 1) void gemm_pv_mma(float* __restrict__ out)
{
    extern __shared__ char smem[];
    const uint32_t s0 = smem_u32(smem);
    const int tid = threadIdx.x;
    const int b = blockIdx.z;
    const int rowBase = blockIdx.y * 128;   // t
    const int colBase = blockIdx.x * 128;   // h

    const fp16* Ah = g_Ph   + ((size_t)b * TGT + rowBase) * SRC;
    const fp16* Bh = g_OETh + ((size_t)b * HD + colBase) * SRC;
    const fp16* Bl = g_OETl + ((size_t)b * HD + colBase) * SRC;

    float acc[4][4][4];
    #pragma unroll
    for (int i = 0; i < 4; ++i)
        #pragma unroll
        for (int j = 0; j < 4; ++j)
            #pragma unroll
            for (int k = 0; k < 4; ++k) acc[i][j][k] = 0.f;

    mma_mainloop<SRC, false>(Ah, nullptr, SRC, Bh, Bl, SRC, acc, s0, tid);

    const int lane = tid & 31, wid = tid >> 5, wm = wid & 1, wn = wid >> 1;
    const int group = lane >> 2, q = lane & 3;
    #pragma unroll
    for (int mi = 0; mi < 4; ++mi) {
        #pragma unroll
        for (int ni = 0; ni < 4; ++ni) {
            const int t0 = rowBase + wm * 64 + mi * 16 + group;
            const int c0 = colBase + wn * 32 + ni * 8 + q * 2;
            *reinterpret_cast<float2*>(out + ((size_t)t0 * BATCH + b) * HD + c0) =
                make_float2(acc[mi][ni][0], acc[mi][ni][1]);
            *reinterpret_cast<float2*>(out + ((size_t)(t0 + 8) * BATCH + b) * HD + c0) =
                make_float2(acc[mi][ni][2], acc[mi][ni][3]);
        }
    }
}

// ----------------------------------------------------------------
extern "C" void kernel_launch(void* const* d_in, const int* in_sizes, int n_in,
                              void* d_out, int out_size)
{
    (void)in_sizes; (void)n_in; (void)out_size;
    const float* out_e = (const float*)d_in[1];   // [SRC][B][2H]
    const float* out_d = (const float*)d_in[2];   // [TGT][B][H]
    float* out = (float*)d_out;                   // [TGT][B][H]

    cudaFuncSetAttribute(gemm_qk_mma, cudaFuncAttributeMaxDynamicSharedMemorySize, SMEM_QK);
    cudaFuncSetAttribute(gemm_pv_mma, cudaFuncAttributeMaxDynamicSharedMemorySize, SMEM_PV);

    const int prepTotal = BATCH * SRC * (HD / 4);
    prep_kernel<<<prepTotal / 256, 256>>>(out_e, out_d);

    dim3 gt(SRC / 32, HD / 32, BATCH);
    transpose_kernel<<<gt, dim3(32, 8)>>>();

    dim3 g1(SRC / 128, TGT / 128, BATCH);                  // 16 x 16 x 16
    gemm_qk_mma<<<g1, 256, SMEM_QK>>>();

    softmax_split_kernel<<<BATCH * TGT, 256>>>();

    dim3 g2(HD / 128, TGT / 128, BATCH);                   // 4 x 16 x 16
    gemm_pv_mma<<<g2, 256, SMEM_PV>>>(out);
}

// round 11
// speedup vs baseline: 2.9454x; 1.0370x over previous
#include <cuda_runtime.h>
#include <cuda_fp16.h>
#include <math.h>
#include <stdint.h>

#define SRC   2048
#define TGT   2048
#define BATCH 16
#define HD    512

typedef __half fp16;

// -------- scratch (device globals; no runtime allocation) --------
__device__ fp16  g_Qh [(size_t)BATCH * TGT * HD];
__device__ fp16  g_Ql [(size_t)BATCH * TGT * HD];
__device__ fp16  g_OEh[(size_t)BATCH * SRC * HD];
__device__ fp16  g_OEl[(size_t)BATCH * SRC * HD];
__device__ float g_ATT[(size_t)BATCH * TGT * SRC];   // fp32 logits
__device__ fp16  g_Ph [(size_t)BATCH * TGT * SRC];   // softmax hi only

// ================= helpers =================
__device__ __forceinline__ uint32_t smem_u32(const void* p) {
    uint32_t a;
    asm("{ .reg .u64 t; cvta.to.shared.u64 t, %1; cvt.u32.u64 %0, t; }"
        : "=r"(a) : "l"(p));
    return a;
}

#define LDSM4(r, addr)                                                        \
    asm volatile("ldmatrix.sync.aligned.m8n8.x4.shared.b16 {%0,%1,%2,%3}, [%4];" \
                 : "=r"((r)[0]), "=r"((r)[1]), "=r"((r)[2]), "=r"((r)[3])     \
                 : "r"(addr))

#define LDSM4T(r, addr)                                                       \
    asm volatile("ldmatrix.sync.aligned.m8n8.x4.trans.shared.b16 {%0,%1,%2,%3}, [%4];" \
                 : "=r"((r)[0]), "=r"((r)[1]), "=r"((r)[2]), "=r"((r)[3])     \
                 : "r"(addr))

#define MMA16816(c, a, b0, b1)                                                \
    asm volatile("mma.sync.aligned.m16n8k16.row.col.f32.f16.f16.f32 "         \
                 "{%0,%1,%2,%3},{%4,%5,%6,%7},{%8,%9},{%0,%1,%2,%3};"         \
                 : "+f"((c)[0]), "+f"((c)[1]), "+f"((c)[2]), "+f"((c)[3])     \
                 : "r"((a)[0]), "r"((a)[1]), "r"((a)[2]), "r"((a)[3]),        \
                   "r"(b0), "r"(b1))

#define CP16(dst, src)                                                        \
    asm volatile("cp.async.cg.shared.global [%0], [%1], 16;" :: "r"(dst), "l"(src))
#define CP_COMMIT() asm volatile("cp.async.commit_group;" ::: "memory")
#define CP_WAIT1()  asm volatile("cp.async.wait_group 1;" ::: "memory")

#define NSTAGE   3
#define KCHUNK   64

// K-major tiles (QK A/B, PV A): 128 rows x 72-halves stride = 18432 B
#define TILE_B   18432u
// NN B tile (PV): 64 k-rows x 136-halves stride = 17408 B
#define BT_STRIDE 136
#define B_TILE_NN 17408u

#define SMEM_QK  (4 * TILE_B * NSTAGE)                    // 221184
#define SMEM_PV  ((TILE_B + 2 * B_TILE_NN) * NSTAGE)      // 159744

// async-copy 128x64 fp16 (row stride ld) -> smem stride 72 ; 4 CP16/thread
__device__ __forceinline__ void cpT(const fp16* __restrict__ g, size_t ld, int k0,
                                    uint32_t sbase, int tid) {
    #pragma unroll
    for (int i = 0; i < 4; ++i) {
        int v = i * 256 + tid;           // 0..1023
        int row = v >> 3;
        int c = v & 7;
        CP16(sbase + (uint32_t)(row * 72 + c * 8) * 2u, g + (size_t)row * ld + k0 + c * 8);
    }
}

// async-copy 64(k) x 128(n) fp16 row-major (row stride ld) -> smem stride 136
__device__ __forceinline__ void cpB_nn(const fp16* __restrict__ g, size_t ld, int k0,
                                       uint32_t sbase, int tid) {
    #pragma unroll
    for (int i = 0; i < 4; ++i) {
        int v = i * 256 + tid;           // 0..1023
        int row = v >> 4;                // 0..63  (k)
        int c = v & 15;                  // 16 x 8-half chunks (n)
        CP16(sbase + (uint32_t)(row * BT_STRIDE + c * 8) * 2u,
             g + (size_t)(k0 + row) * ld + c * 8);
    }
}

// ================= QK mainloop (NT, 3-term split) =================
template <int KTOT>
__device__ __forceinline__ void mma_mainloop_nt(const fp16* __restrict__ Ah, const fp16* __restrict__ Al,
                                                size_t lda,
                                                const fp16* __restrict__ Bh, const fp16* __restrict__ Bl,
                                                size_t ldb,
                                                float (&acc)[4][4][4], uint32_t s0, int tid)
{
    constexpr uint32_t OFF_AL = TILE_B;
    constexpr uint32_t OFF_BH = 2 * TILE_B;
    constexpr uint32_t OFF_BL = 3 * TILE_B;
    constexpr uint32_t STAGE_B = 4 * TILE_B;

    const int NC = KTOT / KCHUNK;
    const int lane = tid & 31;
    const int wid = tid >> 5;
    const int wm = wid & 1;
    const int wn = wid >> 1;

    const int aRow = wm * 64 + (lane & 15);
    const int aCol = (lane >> 4) << 3;
    const int bRow = wn * 32 + (lane & 7) + ((lane >> 4) << 3);
    const int bCol = lane & 8;

    #pragma unroll
    for (int p = 0; p < 2; ++p) {
        uint32_t sb = s0 + p * STAGE_B;
        cpT(Ah, lda, p * KCHUNK, sb,          tid);
        cpT(Al, lda, p * KCHUNK, sb + OFF_AL, tid);
        cpT(Bh, ldb, p * KCHUNK, sb + OFF_BH, tid);
        cpT(Bl, ldb, p * KCHUNK, sb + OFF_BL, tid);
        CP_COMMIT();
    }

    for (int kc = 0; kc < NC; ++kc) {
        CP_WAIT1();
        __syncthreads();

        if (kc + 2 < NC) {
            uint32_t sb = s0 + ((kc + 2) % NSTAGE) * STAGE_B;
            const int k0 = (kc + 2) * KCHUNK;
            cpT(Ah, lda, k0, sb,          tid);
            cpT(Al, lda, k0, sb + OFF_AL, tid);
            cpT(Bh, ldb, k0, sb + OFF_BH, tid);
            cpT(Bl, ldb, k0, sb + OFF_BL, tid);
        }
        CP_COMMIT();

        const uint32_t st = s0 + (kc % NSTAGE) * STAGE_B;
        const uint32_t As_h = st, As_l = st + OFF_AL;
        const uint32_t Bs_h = st + OFF_BH, Bs_l = st + OFF_BL;

        #pragma unroll
        for (int k16 = 0; k16 < 4; ++k16) {
            const int kOff = k16 * 16;
            uint32_t a_h[4][4], a_l[4][4];

            #pragma unroll
            for (int mi = 0; mi < 4; ++mi) {
                uint32_t off = (uint32_t)((aRow + mi * 16) * 72 + kOff + aCol) * 2u;
                LDSM4(a_h[mi], As_h + off);
                LDSM4(a_l[mi], As_l + off);
            }
            #pragma unroll
            for (int n2 = 0; n2 < 2; ++n2) {
                uint32_t b_h[4], b_l[4];
                uint32_t off = (uint32_t)((bRow + n2 * 16) * 72 + kOff + bCol) * 2u;
                LDSM4(b_h, Bs_h + off);
                LDSM4(b_l, Bs_l + off);

                #pragma unroll
                for (int half = 0; half < 2; ++half) {
                    const int ni = n2 * 2 + half;
                    const int sb = half * 2;
                    #pragma unroll
                    for (int mi = 0; mi < 4; ++mi) {
                        MMA16816(acc[mi][ni], a_h[mi], b_h[sb], b_h[sb + 1]); // hi*hi
                        MMA16816(acc[mi][ni], a_h[mi], b_l[sb], b_l[sb + 1]); // hi*lo
                        MMA16816(acc[mi][ni], a_l[mi], b_h[sb], b_h[sb + 1]); // lo*hi
                    }
                }
            }
        }
    }
    __syncthreads();
}

// ================= PV mainloop (NN via ldmatrix.trans, 2-term) =================
// A = P (K-major [t][s]); B = OE row-major [s=k][h=n], fragments via LDSM4T.
template <int KTOT>
__device__ __forceinline__ void mma_mainloop_nn(const fp16* __restrict__ Ah, size_t lda,
                                                const fp16* __restrict__ Bh, const fp16* __restrict__ Bl,
                                                size_t ldb,
                                                float (&acc)[4][4][4], uint32_t s0, int tid)
{
    constexpr uint32_t OFF_BH = TILE_B;
    constexpr uint32_t OFF_BL = TILE_B + B_TILE_NN;
    constexpr uint32_t STAGE_B = TILE_B + 2 * B_TILE_NN;

    const int NC = KTOT / KCHUNK;
    const int lane = tid & 31;
    const int wid = tid >> 5;
    const int wm = wid & 1;
    const int wn = wid >> 1;

    const int aRow = wm * 64 + (lane & 15);
    const int aCol = (lane >> 4) << 3;
    // trans-B lane map: lanes 0-15 -> k=lane, n-block 0; lanes 16-31 -> k=lane-16, n-block +8
    const int bK = lane & 15;
    const int bN = wn * 32 + ((lane >> 4) << 3);

    #pragma unroll
    for (int p = 0; p < 2; ++p) {
        uint32_t sb = s0 + p * STAGE_B;
        cpT  (Ah, lda, p * KCHUNK, sb,          tid);
        cpB_nn(Bh, ldb, p * KCHUNK, sb + OFF_BH, tid);
        cpB_nn(Bl, ldb, p * KCHUNK, sb + OFF_BL, tid);
        CP_COMMIT();
    }

    for (int kc = 0; kc < NC; ++kc) {
        CP_WAIT1();
        __syncthreads();

        if (kc + 2 < NC) {
            uint32_t sb = s0 + ((kc + 2) % NSTAGE) * STAGE_B;
            const int k0 = (kc + 2) * KCHUNK;
            cpT  (Ah, lda, k0, sb,          tid);
            cpB_nn(Bh, ldb, k0, sb + OFF_BH, tid);
            cpB_nn(Bl, ldb, k0, sb + OFF_BL, tid);
        }
        CP_COMMIT();

        const uint32_t st = s0 + (kc % NSTAGE) * STAGE_B;
        const uint32_t As_h = st;
        const uint32_t Bs_h = st + OFF_BH, Bs_l = st + OFF_BL;

        #pragma unroll
        for (int k16 = 0; k16 < 4; ++k16) {
            const int kOff = k16 * 16;
            uint32_t a_h[4][4];

            #pragma unroll
            for (int mi = 0; mi < 4; ++mi) {
                uint32_t off = (uint32_t)((aRow + mi * 16) * 72 + kOff + aCol) * 2u;
                LDSM4(a_h[mi], As_h + off);
            }
            #pragma unroll
            for (int n2 = 0; n2 < 2; ++n2) {
                uint32_t b_h[4], b_l[4];
                // [k][n] tile: addr = (k * 136 + n) * 2
                uint32_t off = (uint32_t)((kOff + bK) * BT_STRIDE + bN + n2 * 16) * 2u;
                LDSM4T(b_h, Bs_h + off);
                LDSM4T(b_l, Bs_l + off);

                #pragma unroll
                for (int half = 0; half < 2; ++half) {
                    const int ni = n2 * 2 + half;
                    const int sb = half * 2;
                    #pragma unroll
                    for (int mi = 0; mi < 4; ++mi) {
                        MMA16816(acc[mi][ni], a_h[mi], b_h[sb], b_h[sb + 1]); // P*hi
                        MMA16816(acc[mi][ni], a_h[mi], b_l[sb], b_l[sb + 1]); // P*lo
                    }
                }
            }
        }
    }
    __syncthreads();
}

// ----------------------------------------------------------------
// prep: oe = fwd+bwd half sum -> hi/lo fp16 [B][S][H];  q -> hi/lo fp16 [B][T][H]
// ----------------------------------------------------------------
__device__ __forceinline__ void split4(float r0, float r1, float r2, float r3,
                                       uint2& uh, uint2& ul) {
    __half2 h01 = __floats2half2_rn(r0, r1);
    __half2 h23 = __floats2half2_rn(r2, r3);
    __half2 l01 = __floats2half2_rn(r0 - __low2float(h01), r1 - __high2float(h01));
    __half2 l23 = __floats2half2_rn(r2 - __low2float(h23), r3 - __high2float(h23));
    uh = make_uint2(reinterpret_cast<uint32_t&>(h01), reinterpret_cast<uint32_t&>(h23));
    ul = make_uint2(reinterpret_cast<uint32_t&>(l01), reinterpret_cast<uint32_t&>(l23));
}

__global__ __launch_bounds__(256) void prep_kernel(const float* __restrict__ out_e,
                                                   const float* __restrict__ out_d)
{
    const size_t i = (size_t)blockIdx.x * blockDim.x + threadIdx.x;   // B*S*(H/4)
    const size_t total = (size_t)BATCH * SRC * (HD / 4);
    if (i >= total) return;

    const int h4 = (int)(i % (HD / 4));
    const size_t bs = i / (HD / 4);
    const int s = (int)(bs % SRC);
    const int b = (int)(bs / SRC);

    {
        const float4* e0 = reinterpret_cast<const float4*>(out_e + ((size_t)s * BATCH + b) * (2 * HD));
        float4 x = e0[h4];
        float4 y = e0[HD / 4 + h4];
        uint2 uh, ul;
        split4(x.x + y.x, x.y + y.y, x.z + y.z, x.w + y.w, uh, ul);
        reinterpret_cast<uint2*>(g_OEh)[i] = uh;
        reinterpret_cast<uint2*>(g_OEl)[i] = ul;
    }
    {
        const float4* d0 = reinterpret_cast<const float4*>(out_d + ((size_t)s * BATCH + b) * HD);
        float4 q = d0[h4];
        uint2 uh, ul;
        split4(q.x, q.y, q.z, q.w, uh, ul);
        reinterpret_cast<uint2*>(g_Qh)[i] = uh;
        reinterpret_cast<uint2*>(g_Ql)[i] = ul;
    }
}

// ----------------------------------------------------------------
// QK: att[b][t][s] = Q[b][t][:] . OE[b][s][:]  (fp32 logits, fp16 3-term)
// ----------------------------------------------------------------
__global__ __launch_bounds__(256, 1) void gemm_qk_mma()
{
    extern __shared__ char smem[];
    const uint32_t s0 = smem_u32(smem);
    const int tid = threadIdx.x;
    const int b = blockIdx.z;
    const int rowBase = blockIdx.y * 128;
    const int colBase = blockIdx.x * 128;

    const fp16* Ah = g_Qh  + ((size_t)b * TGT + rowBase) * HD;
    const fp16* Al = g_Ql  + ((size_t)b * TGT + rowBase) * HD;
    const fp16* Bh = g_OEh + ((size_t)b * SRC + colBase) * HD;
    const fp16* Bl = g_OEl + ((size_t)b * SRC + colBase) * HD;

    float acc[4][4][4];
    #pragma unroll
    for (int i = 0; i < 4; ++i)
        #pragma unroll
        for (int j = 0; j < 4; ++j)
            #pragma unroll
            for (int k = 0; k < 4; ++k) acc[i][j][k] = 0.f;

    mma_mainloop_nt<HD>(Ah, Al, HD, Bh, Bl, HD, acc, s0, tid);

    float* C = g_ATT + (size_t)b * TGT * SRC;
    const int lane = tid & 31, wid = tid >> 5, wm = wid & 1, wn = wid >> 1;
    const int group = lane >> 2, q = lane & 3;
    #pragma unroll
    for (int mi = 0; mi < 4; ++mi) {
        #pragma unroll
        for (int ni = 0; ni < 4; ++ni) {
            const int r0 = rowBase + wm * 64 + mi * 16 + group;
            const int c0 = colBase + wn * 32 + ni * 8 + q * 2;
            *reinterpret_cast<float2*>(C + (size_t)r0 * SRC + c0) =
                make_float2(acc[mi][ni][0], acc[mi][ni][1]);
            *reinterpret_cast<float2*>(C + (size_t)(r0 + 8) * SRC + c0) =
                make_float2(acc[mi][ni][2], acc[mi][ni][3]);
        }
    }
}

// ----------------------------------------------------------------
// softmax over s, writes fp16 P (hi only)
// ----------------------------------------------------------------
__global__ __launch_bounds__(256) void softmax_split_kernel()
{
    const size_t row = blockIdx.x;
    const float* __restrict__ p = g_ATT + row * SRC;
    fp16* __restrict__ ph = g_Ph + row * SRC;
    const int tid = threadIdx.x;

    __shared__ float redm[8];
    __shared__ float reds[8];

    float v[8];
    float m = -INFINITY;
    #pragma unroll
    for (int i = 0; i < 8; ++i) {
        v[i] = p[tid + i * 256];
        m = fmaxf(m, v[i]);
    }
    #pragma unroll
    for (int o = 16; o > 0; o >>= 1) m = fmaxf(m, __shfl_xor_sync(0xffffffffu, m, o));
    if ((tid & 31) == 0) redm[tid >> 5] = m;
    __syncthreads();
    float mAll = redm[0];
    #pragma unroll
    for (int w = 1; w < 8; ++w) mAll = fmaxf(mAll, redm[w]);

    float s = 0.f;
    #pragma unroll
    for (int i = 0; i < 8; ++i) {
        v[i] = __expf(v[i] - mAll);
        s += v[i];
    }
    #pragma unroll
    for (int o = 16; o > 0; o >>= 1) s += __shfl_xor_sync(0xffffffffu, s, o);
    if ((tid & 31) == 0) reds[tid >> 5] = s;
    __syncthreads();
    float sAll = 0.f;
    #pragma unroll
    for (int w = 0; w < 8; ++w) sAll += reds[w];

    const float inv = 1.0f / sAll;
    #pragma unroll
    for (int i = 0; i < 8; ++i)
        ph[tid + i * 256] = __float2half_rn(v[i] * inv);
}

// ----------------------------------------------------------------
// PV: out[t][b][h] = sum_s P[b][t][s] * OE[b][s][h]   (NN, trans-B, 2-term)
// ----------------------------------------------------------------
__global__ __launch_bounds__(256, 1) void gemm_pv_mma(float* __restrict__ out)
{
    extern __shared__ char smem[];
    const uint32_t s0 = smem_u32(smem);
    const int tid = threadIdx.x;
    const int b = blockIdx.z;
    const int rowBase = blockIdx.y * 128;   // t
    const int colBase = blockIdx.x * 128;   // h

    const fp16* Ah = g_Ph  + ((size_t)b * TGT + rowBase) * SRC;
    const fp16* Bh = g_OEh + (size_t)b * SRC * HD + colBase;
    const fp16* Bl = g_OEl + (size_t)b * SRC * HD + colBase;

    float acc[4][4][4];
    #pragma unroll
    for (int i = 0; i < 4; ++i)
        #pragma unroll
        for (int j = 0; j < 4; ++j)
            #pragma unroll
            for (int k = 0; k < 4; ++k) acc[i][j][k] = 0.f;

    mma_mainloop_nn<SRC>(Ah, SRC, Bh, Bl, HD, acc, s0, tid);

    const int lane = tid & 31, wid = tid >> 5, wm = wid & 1, wn = wid >> 1;
    const int group = lane >> 2, q = lane & 3;
    #pragma unroll
    for (int mi = 0; mi < 4; ++mi) {
        #pragma unroll
        for (int ni = 0; ni < 4; ++ni) {
            const int t0 = rowBase + wm * 64 + mi * 16 + group;
            const int c0 = colBase + wn * 32 + ni * 8 + q * 2;
            *reinterpret_cast<float2*>(out + ((size_t)t0 * BATCH + b) * HD + c0) =
                make_float2(acc[mi][ni][0], acc[mi][ni][1]);
            *reinterpret_cast<float2*>(out + ((size_t)(t0 + 8) * BATCH + b) * HD + c0) =
                make_float2(acc[mi][ni][2], acc[mi][ni][3]);
        }
    }
}

// ----------------------------------------------------------------
extern "C" void kernel_launch(void* const* d_in, const int* in_sizes, int n_in,
                              void* d_out, int out_size)
{
    (void)in_sizes; (void)n_in; (void)out_size;
    const float* out_e = (const float*)d_in[1];   // [SRC][B][2H]
    const float* out_d = (const float*)d_in[2];   // [TGT][B][H]
    float* out = (float*)d_out;                   // [TGT][B][H]

    cudaFuncSetAttribute(gemm_qk_mma, cudaFuncAttributeMaxDynamicSharedMemorySize, SMEM_QK);
    cudaFuncSetAttribute(gemm_pv_mma, cudaFuncAttributeMaxDynamicSharedMemorySize, SMEM_PV);

    const int prepTotal = BATCH * SRC * (HD / 4);
    prep_kernel<<<prepTotal / 256, 256>>>(out_e, out_d);

    dim3 g1(SRC / 128, TGT / 128, BATCH);                  // 16 x 16 x 16
    gemm_qk_mma<<<g1, 256, SMEM_QK>>>();

    softmax_split_kernel<<<BATCH * TGT, 256>>>();

    dim3 g2(HD / 128, TGT / 128, BATCH);                   // 4 x 16 x 16
    gemm_pv_mma<<<g2, 256, SMEM_PV>>>(out);
}

// round 13
// speedup vs baseline: 3.2094x; 1.0896x over previous
#include <cuda_runtime.h>
#include <cuda_fp16.h>
#include <math.h>
#include <stdint.h>

#define SRC   2048
#define TGT   2048
#define BATCH 16
#define HD    512

typedef __half fp16;

// -------- scratch (device globals; no runtime allocation) --------
__device__ fp16  g_Qh [(size_t)BATCH * TGT * HD];
__device__ fp16  g_Ql [(size_t)BATCH * TGT * HD];
__device__ fp16  g_OEh[(size_t)BATCH * SRC * HD];
__device__ fp16  g_OEl[(size_t)BATCH * SRC * HD];
__device__ float g_ATT[(size_t)BATCH * TGT * SRC];   // fp32 logits
__device__ fp16  g_Ph [(size_t)BATCH * TGT * SRC];   // softmax hi only

// ================= helpers =================
__device__ __forceinline__ uint32_t smem_u32(const void* p) {
    uint32_t a;
    asm("{ .reg .u64 t; cvta.to.shared.u64 t, %1; cvt.u32.u64 %0, t; }"
        : "=r"(a) : "l"(p));
    return a;
}

#define LDSM4(r, addr)                                                        \
    asm volatile("ldmatrix.sync.aligned.m8n8.x4.shared.b16 {%0,%1,%2,%3}, [%4];" \
                 : "=r"((r)[0]), "=r"((r)[1]), "=r"((r)[2]), "=r"((r)[3])     \
                 : "r"(addr))

#define LDSM4T(r, addr)                                                       \
    asm volatile("ldmatrix.sync.aligned.m8n8.x4.trans.shared.b16 {%0,%1,%2,%3}, [%4];" \
                 : "=r"((r)[0]), "=r"((r)[1]), "=r"((r)[2]), "=r"((r)[3])     \
                 : "r"(addr))

#define MMA16816(c, a, b0, b1)                                                \
    asm volatile("mma.sync.aligned.m16n8k16.row.col.f32.f16.f16.f32 "         \
                 "{%0,%1,%2,%3},{%4,%5,%6,%7},{%8,%9},{%0,%1,%2,%3};"         \
                 : "+f"((c)[0]), "+f"((c)[1]), "+f"((c)[2]), "+f"((c)[3])     \
                 : "r"((a)[0]), "r"((a)[1]), "r"((a)[2]), "r"((a)[3]),        \
                   "r"(b0), "r"(b1))

#define CP16(dst, src)                                                        \
    asm volatile("cp.async.cg.shared.global [%0], [%1], 16;" :: "r"(dst), "l"(src))
#define CP_COMMIT() asm volatile("cp.async.commit_group;" ::: "memory")
#define CP_WAIT0()  asm volatile("cp.async.wait_group 0;" ::: "memory")

// ---------- QK tiles: K-chunk 32, row stride 40 halves ----------
#define QK_KCHUNK   32
#define QK_TILE_B   10240u                    // 128 x 40 x 2
#define QK_STAGE_B  (4 * QK_TILE_B)           // Ah|Al|Bh|Bl = 40960
#define SMEM_QK     (2 * QK_STAGE_B)          // 81920  -> 2 CTAs/SM

// ---------- PV tiles: K-chunk 64 ----------
#define PV_KCHUNK   64
#define A_TILE_B    18432u                    // 128 x 72 x 2   (K-major A)
#define BT_STRIDE   136
#define B_TILE_NN   17408u                    // 64 x 136 x 2   (NN B)
#define PV_STAGE_B  (A_TILE_B + 2 * B_TILE_NN)  // 53248
#define SMEM_PV     (2 * PV_STAGE_B)          // 106496 -> 2 CTAs/SM

// async-copy 128x32 fp16 (row stride ld) -> smem stride 40 ; 2 CP16/thread
__device__ __forceinline__ void cpQK(const fp16* __restrict__ g, size_t ld, int k0,
                                     uint32_t sbase, int tid) {
    #pragma unroll
    for (int i = 0; i < 2; ++i) {
        int v = i * 256 + tid;           // 0..511
        int row = v >> 2;
        int c = v & 3;
        CP16(sbase + (uint32_t)(row * 40 + c * 8) * 2u, g + (size_t)row * ld + k0 + c * 8);
    }
}

// async-copy 128x64 fp16 (row stride ld) -> smem stride 72 ; 4 CP16/thread
__device__ __forceinline__ void cpA64(const fp16* __restrict__ g, size_t ld, int k0,
                                      uint32_t sbase, int tid) {
    #pragma unroll
    for (int i = 0; i < 4; ++i) {
        int v = i * 256 + tid;           // 0..1023
        int row = v >> 3;
        int c = v & 7;
        CP16(sbase + (uint32_t)(row * 72 + c * 8) * 2u, g + (size_t)row * ld + k0 + c * 8);
    }
}

// async-copy 64(k) x 128(n) fp16 row-major (row stride ld) -> smem stride 136
__device__ __forceinline__ void cpB_nn(const fp16* __restrict__ g, size_t ld, int k0,
                                       uint32_t sbase, int tid) {
    #pragma unroll
    for (int i = 0; i < 4; ++i) {
        int v = i * 256 + tid;           // 0..1023
        int row = v >> 4;                // 0..63  (k)
        int c = v & 15;                  // 16 x 8-half chunks (n)
        CP16(sbase + (uint32_t)(row * BT_STRIDE + c * 8) * 2u,
             g + (size_t)(k0 + row) * ld + c * 8);
    }
}

// ================= QK mainloop (NT, 3-term, 2-stage, K32) =================
template <int KTOT>
__device__ __forceinline__ void mma_mainloop_nt(const fp16* __restrict__ Ah, const fp16* __restrict__ Al,
                                                size_t lda,
                                                const fp16* __restrict__ Bh, const fp16* __restrict__ Bl,
                                                size_t ldb,
                                                float (&acc)[4][4][4], uint32_t s0, int tid)
{
    const int NC = KTOT / QK_KCHUNK;
    const int lane = tid & 31;
    const int wid = tid >> 5;
    const int wm = wid & 1;
    const int wn = wid >> 1;

    const int aRow = wm * 64 + (lane & 15);
    const int aCol = (lane >> 4) << 3;
    const int bRow = wn * 32 + (lane & 7) + ((lane >> 4) << 3);
    const int bCol = lane & 8;

    // prologue: chunk 0 -> buf 0
    {
        uint32_t sb = s0;
        cpQK(Ah, lda, 0, sb,                  tid);
        cpQK(Al, lda, 0, sb + QK_TILE_B,      tid);
        cpQK(Bh, ldb, 0, sb + 2 * QK_TILE_B,  tid);
        cpQK(Bl, ldb, 0, sb + 3 * QK_TILE_B,  tid);
        CP_COMMIT();
    }

    for (int kc = 0; kc < NC; ++kc) {
        CP_WAIT0();                      // chunk kc resident (only pending group)
        __syncthreads();                 // buf of kc-1 (== buf of kc+1) free

        if (kc + 1 < NC) {
            uint32_t sb = s0 + ((kc + 1) & 1) * QK_STAGE_B;
            const int k0 = (kc + 1) * QK_KCHUNK;
            cpQK(Ah, lda, k0, sb,                 tid);
            cpQK(Al, lda, k0, sb + QK_TILE_B,     tid);
            cpQK(Bh, ldb, k0, sb + 2 * QK_TILE_B, tid);
            cpQK(Bl, ldb, k0, sb + 3 * QK_TILE_B, tid);
            CP_COMMIT();
        }

        const uint32_t st = s0 + (kc & 1) * QK_STAGE_B;
        const uint32_t As_h = st, As_l = st + QK_TILE_B;
        const uint32_t Bs_h = st + 2 * QK_TILE_B, Bs_l = st + 3 * QK_TILE_B;

        #pragma unroll
        for (int k16 = 0; k16 < 2; ++k16) {
            const int kOff = k16 * 16;
            uint32_t a_h[4][4], a_l[4][4];

            #pragma unroll
            for (int mi = 0; mi < 4; ++mi) {
                uint32_t off = (uint32_t)((aRow + mi * 16) * 40 + kOff + aCol) * 2u;
                LDSM4(a_h[mi], As_h + off);
                LDSM4(a_l[mi], As_l + off);
            }
            #pragma unroll
            for (int n2 = 0; n2 < 2; ++n2) {
                uint32_t b_h[4], b_l[4];
                uint32_t off = (uint32_t)((bRow + n2 * 16) * 40 + kOff + bCol) * 2u;
                LDSM4(b_h, Bs_h + off);
                LDSM4(b_l, Bs_l + off);

                #pragma unroll
                for (int half = 0; half < 2; ++half) {
                    const int ni = n2 * 2 + half;
                    const int sb = half * 2;
                    #pragma unroll
                    for (int mi = 0; mi < 4; ++mi) {
                        MMA16816(acc[mi][ni], a_h[mi], b_h[sb], b_h[sb + 1]); // hi*hi
                        MMA16816(acc[mi][ni], a_h[mi], b_l[sb], b_l[sb + 1]); // hi*lo
                        MMA16816(acc[mi][ni], a_l[mi], b_h[sb], b_h[sb + 1]); // lo*hi
                    }
                }
            }
        }
    }
    __syncthreads();
}

// ================= PV mainloop (NN via ldmatrix.trans, 2-term, 2-stage, K64) =================
template <int KTOT>
__device__ __forceinline__ void mma_mainloop_nn(const fp16* __restrict__ Ah, size_t lda,
                                                const fp16* __restrict__ Bh, const fp16* __restrict__ Bl,
                                                size_t ldb,
                                                float (&acc)[4][4][4], uint32_t s0, int tid)
{
    constexpr uint32_t OFF_BH = A_TILE_B;
    constexpr uint32_t OFF_BL = A_TILE_B + B_TILE_NN;

    const int NC = KTOT / PV_KCHUNK;
    const int lane = tid & 31;
    const int wid = tid >> 5;
    const int wm = wid & 1;
    const int wn = wid >> 1;

    const int aRow = wm * 64 + (lane & 15);
    const int aCol = (lane >> 4) << 3;
    const int bK = lane & 15;
    const int bN = wn * 32 + ((lane >> 4) << 3);

    // prologue: chunk 0 -> buf 0
    {
        cpA64 (Ah, lda, 0, s0,          tid);
        cpB_nn(Bh, ldb, 0, s0 + OFF_BH, tid);
        cpB_nn(Bl, ldb, 0, s0 + OFF_BL, tid);
        CP_COMMIT();
    }

    for (int kc = 0; kc < NC; ++kc) {
        CP_WAIT0();
        __syncthreads();

        if (kc + 1 < NC) {
            uint32_t sb = s0 + ((kc + 1) & 1) * PV_STAGE_B;
            const int k0 = (kc + 1) * PV_KCHUNK;
            cpA64 (Ah, lda, k0, sb,          tid);
            cpB_nn(Bh, ldb, k0, sb + OFF_BH, tid);
            cpB_nn(Bl, ldb, k0, sb + OFF_BL, tid);
            CP_COMMIT();
        }

        const uint32_t st = s0 + (kc & 1) * PV_STAGE_B;
        const uint32_t As_h = st;
        const uint32_t Bs_h = st + OFF_BH, Bs_l = st + OFF_BL;

        #pragma unroll
        for (int k16 = 0; k16 < 4; ++k16) {
            const int kOff = k16 * 16;
            uint32_t a_h[4][4];

            #pragma unroll
            for (int mi = 0; mi < 4; ++mi) {
                uint32_t off = (uint32_t)((aRow + mi * 16) * 72 + kOff + aCol) * 2u;
                LDSM4(a_h[mi], As_h + off);
            }
            #pragma unroll
            for (int n2 = 0; n2 < 2; ++n2) {
                uint32_t b_h[4], b_l[4];
                uint32_t off = (uint32_t)((kOff + bK) * BT_STRIDE + bN + n2 * 16) * 2u;
                LDSM4T(b_h, Bs_h + off);
                LDSM4T(b_l, Bs_l + off);

                #pragma unroll
                for (int half = 0; half < 2; ++half) {
                    const int ni = n2 * 2 + half;
                    const int sb = half * 2;
                    #pragma unroll
                    for (int mi = 0; mi < 4; ++mi) {
                        MMA16816(acc[mi][ni], a_h[mi], b_h[sb], b_h[sb + 1]); // P*hi
                        MMA16816(acc[mi][ni], a_h[mi], b_l[sb], b_l[sb + 1]); // P*lo
                    }
                }
            }
        }
    }
    __syncthreads();
}

// ----------------------------------------------------------------
// prep: oe = fwd+bwd half sum -> hi/lo fp16;  q -> hi/lo fp16
// ----------------------------------------------------------------
__device__ __forceinline__ void split4(float r0, float r1, float r2, float r3,
                                       uint2& uh, uint2& ul) {
    __half2 h01 = __floats2half2_rn(r0, r1);
    __half2 h23 = __floats2half2_rn(r2, r3);
    __half2 l01 = __floats2half2_rn(r0 - __low2float(h01), r1 - __high2float(h01));
    __half2 l23 = __floats2half2_rn(r2 - __low2float(h23), r3 - __high2float(h23));
    uh = make_uint2(reinterpret_cast<uint32_t&>(h01), reinterpret_cast<uint32_t&>(h23));
    ul = make_uint2(reinterpret_cast<uint32_t&>(l01), reinterpret_cast<uint32_t&>(l23));
}

__global__ __launch_bounds__(256) void prep_kernel(const float* __restrict__ out_e,
                                                   const float* __restrict__ out_d)
{
    const size_t i = (size_t)blockIdx.x * blockDim.x + threadIdx.x;
    const size_t total = (size_t)BATCH * SRC * (HD / 4);
    if (i >= total) return;

    const int h4 = (int)(i % (HD / 4));
    const size_t bs = i / (HD / 4);
    const int s = (int)(bs % SRC);
    const int b = (int)(bs / SRC);

    {
        const float4* e0 = reinterpret_cast<const float4*>(out_e + ((size_t)s * BATCH + b) * (2 * HD));
        float4 x = e0[h4];
        float4 y = e0[HD / 4 + h4];
        uint2 uh, ul;
        split4(x.x + y.x, x.y + y.y, x.z + y.z, x.w + y.w, uh, ul);
        reinterpret_cast<uint2*>(g_OEh)[i] = uh;
        reinterpret_cast<uint2*>(g_OEl)[i] = ul;
    }
    {
        const float4* d0 = reinterpret_cast<const float4*>(out_d + ((size_t)s * BATCH + b) * HD);
        float4 q = d0[h4];
        uint2 uh, ul;
        split4(q.x, q.y, q.z, q.w, uh, ul);
        reinterpret_cast<uint2*>(g_Qh)[i] = uh;
        reinterpret_cast<uint2*>(g_Ql)[i] = ul;
    }
}

// ----------------------------------------------------------------
// QK: att[b][t][s] = Q[b][t][:] . OE[b][s][:]  (fp32 logits, fp16 3-term)
// ----------------------------------------------------------------
__global__ __launch_bounds__(256, 2) void gemm_qk_mma()
{
    extern __shared__ char smem[];
    const uint32_t s0 = smem_u32(smem);
    const int tid = threadIdx.x;
    const int b = blockIdx.z;
    const int rowBase = blockIdx.y * 128;
    const int colBase = blockIdx.x * 128;

    const fp16* Ah = g_Qh  + ((size_t)b * TGT + rowBase) * HD;
    const fp16* Al = g_Ql  + ((size_t)b * TGT + rowBase) * HD;
    const fp16* Bh = g_OEh + ((size_t)b * SRC + colBase) * HD;
    const fp16* Bl = g_OEl + ((size_t)b * SRC + colBase) * HD;

    float acc[4][4][4];
    #pragma unroll
    for (int i = 0; i < 4; ++i)
        #pragma unroll
        for (int j = 0; j < 4; ++j)
            #pragma unroll
            for (int k = 0; k < 4; ++k) acc[i][j][k] = 0.f;

    mma_mainloop_nt<HD>(Ah, Al, HD, Bh, Bl, HD, acc, s0, tid);

    float* C = g_ATT + (size_t)b * TGT * SRC;
    const int lane = tid & 31, wid = tid >> 5, wm = wid & 1, wn = wid >> 1;
    const int group = lane >> 2, q = lane & 3;
    #pragma unroll
    for (int mi = 0; mi < 4; ++mi) {
        #pragma unroll
        for (int ni = 0; ni < 4; ++ni) {
            const int r0 = rowBase + wm * 64 + mi * 16 + group;
            const int c0 = colBase + wn * 32 + ni * 8 + q * 2;
            *reinterpret_cast<float2*>(C + (size_t)r0 * SRC + c0) =
                make_float2(acc[mi][ni][0], acc[mi][ni][1]);
            *reinterpret_cast<float2*>(C + (size_t)(r0 + 8) * SRC + c0) =
                make_float2(acc[mi][ni][2], acc[mi][ni][3]);
        }
    }
}

// ----------------------------------------------------------------
// softmax over s, writes fp16 P (hi only)
// ----------------------------------------------------------------
__global__ __launch_bounds__(256) void softmax_split_kernel()
{
    const size_t row = blockIdx.x;
    const float* __restrict__ p = g_ATT + row * SRC;
    fp16* __restrict__ ph = g_Ph + row * SRC;
    const int tid = threadIdx.x;

    __shared__ float redm[8];
    __shared__ float reds[8];

    float v[8];
    float m = -INFINITY;
    #pragma unroll
    for (int i = 0; i < 8; ++i) {
        v[i] = p[tid + i * 256];
        m = fmaxf(m, v[i]);
    }
    #pragma unroll
    for (int o = 16; o > 0; o >>= 1) m = fmaxf(m, __shfl_xor_sync(0xffffffffu, m, o));
    if ((tid & 31) == 0) redm[tid >> 5] = m;
    __syncthreads();
    float mAll = redm[0];
    #pragma unroll
    for (int w = 1; w < 8; ++w) mAll = fmaxf(mAll, redm[w]);

    float s = 0.f;
    #pragma unroll
    for (int i = 0; i < 8; ++i) {
        v[i] = __expf(v[i] - mAll);
        s += v[i];
    }
    #pragma unroll
    for (int o = 16; o > 0; o >>= 1) s += __shfl_xor_sync(0xffffffffu, s, o);
    if ((tid & 31) == 0) reds[tid >> 5] = s;
    __syncthreads();
    float sAll = 0.f;
    #pragma unroll
    for (int w = 0; w < 8; ++w) sAll += reds[w];

    const float inv = 1.0f / sAll;
    #pragma unroll
    for (int i = 0; i < 8; ++i)
        ph[tid + i * 256] = __float2half_rn(v[i] * inv);
}

// ----------------------------------------------------------------
// PV: out[t][b][h] = sum_s P[b][t][s] * OE[b][s][h]   (NN, trans-B, 2-term)
// ----------------------------------------------------------------
__global__ __launch_bounds__(256, 2) void gemm_pv_mma(float* __restrict__ out)
{
    extern __shared__ char smem[];
    const uint32_t s0 = smem_u32(smem);
    const int tid = threadIdx.x;
    const int b = blockIdx.z;
    const int rowBase = blockIdx.y * 128;   // t
    const int colBase = blockIdx.x * 128;   // h

    const fp16* Ah = g_Ph  + ((size_t)b * TGT + rowBase) * SRC;
    const fp16* Bh = g_OEh + (size_t)b * SRC * HD + colBase;
    const fp16* Bl = g_OEl + (size_t)b * SRC * HD + colBase;

    float acc[4][4][4];
    #pragma unroll
    for (int i = 0; i < 4; ++i)
        #pragma unroll
        for (int j = 0; j < 4; ++j)
            #pragma unroll
            for (int k = 0; k < 4; ++k) acc[i][j][k] = 0.f;

    mma_mainloop_nn<SRC>(Ah, SRC, Bh, Bl, HD, acc, s0, tid);

    const int lane = tid & 31, wid = tid >> 5, wm = wid & 1, wn = wid >> 1;
    const int group = lane >> 2, q = lane & 3;
    #pragma unroll
    for (int mi = 0; mi < 4; ++mi) {
        #pragma unroll
        for (int ni = 0; ni < 4; ++ni) {
            const int t0 = rowBase + wm * 64 + mi * 16 + group;
            const int c0 = colBase + wn * 32 + ni * 8 + q * 2;
            *reinterpret_cast<float2*>(out + ((size_t)t0 * BATCH + b) * HD + c0) =
                make_float2(acc[mi][ni][0], acc[mi][ni][1]);
            *reinterpret_cast<float2*>(out + ((size_t)(t0 + 8) * BATCH + b) * HD + c0) =
                make_float2(acc[mi][ni][2], acc[mi][ni][3]);
        }
    }
}

// ----------------------------------------------------------------
extern "C" void kernel_launch(void* const* d_in, const int* in_sizes, int n_in,
                              void* d_out, int out_size)
{
    (void)in_sizes; (void)n_in; (void)out_size;
    const float* out_e = (const float*)d_in[1];   // [SRC][B][2H]
    const float* out_d = (const float*)d_in[2];   // [TGT][B][H]
    float* out = (float*)d_out;                   // [TGT][B][H]

    cudaFuncSetAttribute(gemm_qk_mma, cudaFuncAttributeMaxDynamicSharedMemorySize, SMEM_QK);
    cudaFuncSetAttribute(gemm_pv_mma, cudaFuncAttributeMaxDynamicSharedMemorySize, SMEM_PV);

    const int prepTotal = BATCH * SRC * (HD / 4);
    prep_kernel<<<prepTotal / 256, 256>>>(out_e, out_d);

    dim3 g1(SRC / 128, TGT / 128, BATCH);                  // 16 x 16 x 16
    gemm_qk_mma<<<g1, 256, SMEM_QK>>>();

    softmax_split_kernel<<<BATCH * TGT, 256>>>();

    dim3 g2(HD / 128, TGT / 128, BATCH);                   // 4 x 16 x 16
    gemm_pv_mma<<<g2, 256, SMEM_PV>>>(out);
}